// round 1
// baseline (speedup 1.0000x reference)
#include <cuda_runtime.h>
#include <cuda_bf16.h>
#include <math.h>

#define Bz 8
#define Tt 1024
#define Ss 1024
#define Dm 512
#define Hh 8
#define DK 64
#define FFd 2048
#define NL 6

// ---------------- scratch (device globals; no runtime allocation) ----------------
__device__ float g_x  [Bz*Tt*Dm];         // running activations
__device__ float g_q  [Bz*Tt*Dm];
__device__ float g_k  [Bz*Ss*Dm];
__device__ float g_v  [Bz*Ss*Dm];
__device__ float g_s  [(size_t)Bz*Hh*Tt*Ss]; // attention scores/probs (256 MB)
__device__ float g_ctx[Bz*Tt*Dm];
__device__ float g_h  [Bz*Tt*FFd];        // FFN hidden
__device__ float g_t  [Bz*Tt*Dm];         // pre-LN temp

// ---------------- embedding + sinusoidal PE (padding_idx = 0) ----------------
__global__ void embed_k(const int* __restrict__ dec, const float* __restrict__ emb,
                        float* __restrict__ x)
{
    int bt = blockIdx.x;              // 0..B*T-1
    int tpos = bt & (Tt - 1);
    int tok = dec[bt];
    int t = threadIdx.x;              // 128 threads
    const double neg_ln1e4_over_d = -9.210340371976184 / (double)Dm;
#pragma unroll
    for (int i = 0; i < 4; i++) {
        int d = t + 128 * i;
        int pair = d >> 1;
        double div = exp((double)(2 * pair) * neg_ln1e4_over_d);
        double ang = (double)tpos * div;
        float pe = (float)((d & 1) ? cos(ang) : sin(ang));
        float e = (tok == 0) ? 0.0f : emb[(size_t)tok * Dm + d];
        x[(size_t)bt * Dm + d] = e + pe;
    }
}

// ---------------- generic batched SGEMM: C = A @ B, optional ReLU ----------------
// batch index z: offset = (z/bdiv)*s? + (z%bdiv)*s?2  for A, B, C.
// Requires M%64==0, N%64==0, K%16==0 (true for every call here).
__global__ void gemm_nn(const float* __restrict__ A, int lda, long sA, long sA2,
                        const float* __restrict__ B, int ldb, long sB, long sB2,
                        float* __restrict__ C, int ldc, long sC, long sC2,
                        int M, int N, int K, int bdiv, int relu)
{
    int z = blockIdx.z;
    int zo = z / bdiv, zi = z % bdiv;
    A += (long)zo * sA + (long)zi * sA2;
    B += (long)zo * sB + (long)zi * sB2;
    C += (long)zo * sC + (long)zi * sC2;

    __shared__ float As[64][17];       // As[m][k]
    __shared__ float Bs[16][68];       // Bs[k][n]

    int tid = threadIdx.x;             // 256 threads
    int tx = tid & 15, ty = tid >> 4;
    int m0 = blockIdx.y * 64, n0 = blockIdx.x * 64;

    float acc[4][4];
#pragma unroll
    for (int i = 0; i < 4; i++)
#pragma unroll
        for (int j = 0; j < 4; j++) acc[i][j] = 0.0f;

    for (int k0 = 0; k0 < K; k0 += 16) {
#pragma unroll
        for (int e = tid; e < 1024; e += 256) {
            int m = e >> 4, k = e & 15;
            As[m][k] = A[(long)(m0 + m) * lda + k0 + k];
        }
#pragma unroll
        for (int e = tid; e < 1024; e += 256) {
            int k = e >> 6, n = e & 63;
            Bs[k][n] = B[(long)(k0 + k) * ldb + n0 + n];
        }
        __syncthreads();
#pragma unroll
        for (int k = 0; k < 16; k++) {
            float a0 = As[ty * 4 + 0][k];
            float a1 = As[ty * 4 + 1][k];
            float a2 = As[ty * 4 + 2][k];
            float a3 = As[ty * 4 + 3][k];
            float b0 = Bs[k][tx * 4 + 0];
            float b1 = Bs[k][tx * 4 + 1];
            float b2 = Bs[k][tx * 4 + 2];
            float b3 = Bs[k][tx * 4 + 3];
            acc[0][0] += a0 * b0; acc[0][1] += a0 * b1; acc[0][2] += a0 * b2; acc[0][3] += a0 * b3;
            acc[1][0] += a1 * b0; acc[1][1] += a1 * b1; acc[1][2] += a1 * b2; acc[1][3] += a1 * b3;
            acc[2][0] += a2 * b0; acc[2][1] += a2 * b1; acc[2][2] += a2 * b2; acc[2][3] += a2 * b3;
            acc[3][0] += a3 * b0; acc[3][1] += a3 * b1; acc[3][2] += a3 * b2; acc[3][3] += a3 * b3;
        }
        __syncthreads();
    }
#pragma unroll
    for (int i = 0; i < 4; i++)
#pragma unroll
        for (int j = 0; j < 4; j++) {
            float vv = acc[i][j];
            if (relu) vv = fmaxf(vv, 0.0f);
            C[(long)(m0 + ty * 4 + i) * ldc + n0 + tx * 4 + j] = vv;
        }
}

// ---------------- Q K^T scores with scale + mask fused ----------------
// mode 0: self (causal + dec pad), mode 1: cross (enc pad)
__global__ void scores_k(const float* __restrict__ Q, const float* __restrict__ Km,
                         float* __restrict__ S, const int* __restrict__ tok,
                         int mode, int Tq, int Tk)
{
    int z = blockIdx.z;                 // b*H + h
    int b = z >> 3, h = z & 7;
    int q0 = blockIdx.y * 32, k0 = blockIdx.x * 32;
    const float* Qb = Q + ((long)b * Tq) * Dm + h * DK;
    const float* Kb = Km + ((long)b * Tk) * Dm + h * DK;

    __shared__ float Qs[32][65], Ks[32][65];
    int tid = threadIdx.y * 32 + threadIdx.x;
    for (int e = tid; e < 2048; e += 1024) {
        int r = e >> 6, d = e & 63;
        Qs[r][d] = Qb[(long)(q0 + r) * Dm + d];
        Ks[r][d] = Kb[(long)(k0 + r) * Dm + d];
    }
    __syncthreads();

    int qi = threadIdx.y, ki = threadIdx.x;
    float sum = 0.0f;
#pragma unroll
    for (int d = 0; d < 64; d++) sum += Qs[qi][d] * Ks[ki][d];
    sum *= 0.125f;   // 1/sqrt(64)

    int q = q0 + qi, k = k0 + ki;
    bool masked;
    if (mode == 0) masked = (k > q) || (tok[b * Tk + k] == 0);
    else           masked = (tok[b * Tk + k] == 0);
    if (masked) sum = -1e9f;
    S[((long)z * Tq + q) * Tk + k] = sum;
}

// ---------------- row softmax over Tk=1024 ----------------
__global__ void softmax_k(float* __restrict__ S)
{
    float* row = S + (size_t)blockIdx.x * 1024;
    int t = threadIdx.x;               // 256
    float v[4];
    float m = -INFINITY;
#pragma unroll
    for (int i = 0; i < 4; i++) { v[i] = row[t + i * 256]; m = fmaxf(m, v[i]); }
    __shared__ float red[256];
    red[t] = m; __syncthreads();
    for (int s = 128; s > 0; s >>= 1) { if (t < s) red[t] = fmaxf(red[t], red[t + s]); __syncthreads(); }
    m = red[0]; __syncthreads();
    float sum = 0.0f;
#pragma unroll
    for (int i = 0; i < 4; i++) { v[i] = expf(v[i] - m); sum += v[i]; }
    red[t] = sum; __syncthreads();
    for (int s = 128; s > 0; s >>= 1) { if (t < s) red[t] += red[t + s]; __syncthreads(); }
    float inv = 1.0f / red[0];
#pragma unroll
    for (int i = 0; i < 4; i++) row[t + i * 256] = v[i] * inv;
}

// ---------------- out = LayerNorm(a + b) over D=512 ----------------
__global__ void add_ln_k(const float* __restrict__ A, const float* __restrict__ Bres,
                         float* __restrict__ O)
{
    size_t r = blockIdx.x;
    const float* a = A + r * Dm;
    const float* b = Bres + r * Dm;
    int t = threadIdx.x;               // 128
    float v[4];
    float s = 0.0f;
#pragma unroll
    for (int i = 0; i < 4; i++) { v[i] = a[t + 128 * i] + b[t + 128 * i]; s += v[i]; }
    __shared__ float red[128];
    red[t] = s; __syncthreads();
    for (int st = 64; st > 0; st >>= 1) { if (t < st) red[t] += red[t + st]; __syncthreads(); }
    float mu = red[0] * (1.0f / Dm);
    __syncthreads();
    float s2 = 0.0f;
#pragma unroll
    for (int i = 0; i < 4; i++) { float d = v[i] - mu; s2 += d * d; }
    red[t] = s2; __syncthreads();
    for (int st = 64; st > 0; st >>= 1) { if (t < st) red[t] += red[t + st]; __syncthreads(); }
    float inv = rsqrtf(red[0] * (1.0f / Dm) + 1e-5f);
#pragma unroll
    for (int i = 0; i < 4; i++) O[r * Dm + t + 128 * i] = (v[i] - mu) * inv;
}

// ---------------- host orchestration ----------------
static float* sym_ptr(const void* sym)
{
    void* p = nullptr;
    cudaGetSymbolAddress(&p, sym);
    return (float*)p;
}

extern "C" void kernel_launch(void* const* d_in, const int* in_sizes, int n_in,
                              void* d_out, int out_size)
{
    const int*   dec      = (const int*)d_in[0];
    const int*   enc_in   = (const int*)d_in[1];
    const float* enc_out  = (const float*)d_in[2];
    const float* emb      = (const float*)d_in[3];
    const float* Wq_self  = (const float*)d_in[4];
    const float* Wk_self  = (const float*)d_in[5];
    const float* Wv_self  = (const float*)d_in[6];
    const float* Wo_self  = (const float*)d_in[7];
    const float* Wq_cross = (const float*)d_in[8];
    const float* Wk_cross = (const float*)d_in[9];
    const float* Wv_cross = (const float*)d_in[10];
    const float* Wo_cross = (const float*)d_in[11];
    const float* W1       = (const float*)d_in[12];
    const float* W2       = (const float*)d_in[13];

    float* x   = sym_ptr(g_x);
    float* q   = sym_ptr(g_q);
    float* k   = sym_ptr(g_k);
    float* v   = sym_ptr(g_v);
    float* s   = sym_ptr(g_s);
    float* ctx = sym_ptr(g_ctx);
    float* hbf = sym_ptr(g_h);
    float* t1  = sym_ptr(g_t);

    const int M = Bz * Tt;   // 8192 rows for both dec tokens and enc tokens

    embed_k<<<Bz * Tt, 128>>>(dec, emb, x);

    dim3 gProj(Dm / 64, M / 64, 1);       // N=512
    dim3 gFF1(FFd / 64, M / 64, 1);       // N=2048
    dim3 gCtx(1, Tt / 64, Bz * Hh);       // N=64, batched
    dim3 gScore(Ss / 32, Tt / 32, Bz * Hh);
    dim3 bScore(32, 32);
    const long TT = (long)Tt * Ss;

    for (int l = 0; l < NL; l++) {
        const float* wqs = Wq_self  + (long)l * Dm * Dm;
        const float* wks = Wk_self  + (long)l * Dm * Dm;
        const float* wvs = Wv_self  + (long)l * Dm * Dm;
        const float* wos = Wo_self  + (long)l * Dm * Dm;
        const float* wqc = Wq_cross + (long)l * Dm * Dm;
        const float* wkc = Wk_cross + (long)l * Dm * Dm;
        const float* wvc = Wv_cross + (long)l * Dm * Dm;
        const float* woc = Wo_cross + (long)l * Dm * Dm;
        const float* w1  = W1 + (long)l * Dm * FFd;
        const float* w2  = W2 + (long)l * FFd * Dm;

        // ---- self-attention ----
        gemm_nn<<<gProj, 256>>>(x, Dm, 0, 0, wqs, Dm, 0, 0, q, Dm, 0, 0, M, Dm, Dm, 1, 0);
        gemm_nn<<<gProj, 256>>>(x, Dm, 0, 0, wks, Dm, 0, 0, k, Dm, 0, 0, M, Dm, Dm, 1, 0);
        gemm_nn<<<gProj, 256>>>(x, Dm, 0, 0, wvs, Dm, 0, 0, v, Dm, 0, 0, M, Dm, Dm, 1, 0);
        scores_k<<<gScore, bScore>>>(q, k, s, dec, 0, Tt, Tt);
        softmax_k<<<Bz * Hh * Tt, 256>>>(s);
        gemm_nn<<<gCtx, 256>>>(s, Ss, 8 * TT, TT,
                               v, Dm, (long)Tt * Dm, DK,
                               ctx, Dm, (long)Tt * Dm, DK,
                               Tt, DK, Ss, Hh, 0);
        gemm_nn<<<gProj, 256>>>(ctx, Dm, 0, 0, wos, Dm, 0, 0, t1, Dm, 0, 0, M, Dm, Dm, 1, 0);
        add_ln_k<<<M, 128>>>(t1, x, x);

        // ---- cross-attention ----
        gemm_nn<<<gProj, 256>>>(x, Dm, 0, 0, wqc, Dm, 0, 0, q, Dm, 0, 0, M, Dm, Dm, 1, 0);
        gemm_nn<<<gProj, 256>>>(enc_out, Dm, 0, 0, wkc, Dm, 0, 0, k, Dm, 0, 0, M, Dm, Dm, 1, 0);
        gemm_nn<<<gProj, 256>>>(enc_out, Dm, 0, 0, wvc, Dm, 0, 0, v, Dm, 0, 0, M, Dm, Dm, 1, 0);
        scores_k<<<gScore, bScore>>>(q, k, s, enc_in, 1, Tt, Ss);
        softmax_k<<<Bz * Hh * Tt, 256>>>(s);
        gemm_nn<<<gCtx, 256>>>(s, Ss, 8 * TT, TT,
                               v, Dm, (long)Ss * Dm, DK,
                               ctx, Dm, (long)Tt * Dm, DK,
                               Tt, DK, Ss, Hh, 0);
        gemm_nn<<<gProj, 256>>>(ctx, Dm, 0, 0, woc, Dm, 0, 0, t1, Dm, 0, 0, M, Dm, Dm, 1, 0);
        add_ln_k<<<M, 128>>>(t1, x, x);

        // ---- FFN ----
        gemm_nn<<<gFF1, 256>>>(x, Dm, 0, 0, w1, FFd, 0, 0, hbf, FFd, 0, 0, M, FFd, Dm, 1, 1);
        gemm_nn<<<gProj, 256>>>(hbf, FFd, 0, 0, w2, Dm, 0, 0, t1, Dm, 0, 0, M, Dm, FFd, 1, 0);
        add_ln_k<<<M, 128>>>(t1, x, x);
    }

    cudaMemcpyAsync(d_out, x, (size_t)M * Dm * sizeof(float), cudaMemcpyDeviceToDevice);
}

// round 4
// speedup vs baseline: 3.2494x; 3.2494x over previous
#include <cuda_runtime.h>
#include <cuda_bf16.h>
#include <math.h>
#include <stdint.h>

#define Bz 8
#define Tt 1024
#define Ss 1024
#define Dm 512
#define Hh 8
#define DKh 64
#define FFd 2048
#define NL 6

// ---------------- scratch (device globals) ----------------
__device__ float g_x  [Bz*Tt*Dm];
__device__ float g_q  [Bz*Tt*Dm];
__device__ float g_k  [Bz*Ss*Dm];
__device__ float g_v  [Bz*Ss*Dm];
__device__ float g_s  [(size_t)Bz*Hh*Tt*Ss];
__device__ float g_ctx[Bz*Tt*Dm];
__device__ float g_h  [Bz*Tt*FFd];
__device__ float g_t  [Bz*Tt*Dm];
#define WT_L 4194304
__device__ __nv_bfloat16 g_wthi[(size_t)NL*WT_L];
__device__ __nv_bfloat16 g_wtlo[(size_t)NL*WT_L];
__device__ __nv_bfloat16 g_vthi[Bz*Hh*DKh*Ss];
__device__ __nv_bfloat16 g_vtlo[Bz*Hh*DKh*Ss];

// ---------------- helpers ----------------
__device__ __forceinline__ uint32_t smem_u32(const void* p) {
    uint32_t a;
    asm("{ .reg .u64 t; cvta.to.shared.u64 t, %1; cvt.u32.u64 %0, t; }" : "=r"(a) : "l"(p));
    return a;
}
__device__ __forceinline__ uint32_t bf2pack(__nv_bfloat16 a, __nv_bfloat16 b) {
    __nv_bfloat162 t; t.x = a; t.y = b;
    return *reinterpret_cast<uint32_t*>(&t);
}
__device__ __forceinline__ void split8(const float* f, uint4& H, uint4& L) {
    __nv_bfloat16 h[8]; __nv_bfloat16 l[8];
#pragma unroll
    for (int i = 0; i < 8; i++) {
        h[i] = __float2bfloat16(f[i]);
        l[i] = __float2bfloat16(f[i] - __bfloat162float(h[i]));
    }
    H.x = bf2pack(h[0], h[1]); H.y = bf2pack(h[2], h[3]);
    H.z = bf2pack(h[4], h[5]); H.w = bf2pack(h[6], h[7]);
    L.x = bf2pack(l[0], l[1]); L.y = bf2pack(l[2], l[3]);
    L.z = bf2pack(l[4], l[5]); L.w = bf2pack(l[6], l[7]);
}
#define STS128(addr, v) asm volatile("st.shared.v4.b32 [%0], {%1,%2,%3,%4};" :: "r"(addr), "r"((v).x), "r"((v).y), "r"((v).z), "r"((v).w) : "memory")

__device__ __forceinline__ void ldm4(uint32_t* r, uint32_t addr) {
    asm volatile("ldmatrix.sync.aligned.m8n8.x4.shared.b16 {%0,%1,%2,%3}, [%4];"
        : "=r"(r[0]), "=r"(r[1]), "=r"(r[2]), "=r"(r[3]) : "r"(addr));
}
__device__ __forceinline__ void mma16816(float* c, const uint32_t* a, const uint32_t* b) {
    asm volatile("mma.sync.aligned.m16n8k16.row.col.f32.bf16.bf16.f32 "
        "{%0,%1,%2,%3}, {%4,%5,%6,%7}, {%8,%9}, {%0,%1,%2,%3};"
        : "+f"(c[0]), "+f"(c[1]), "+f"(c[2]), "+f"(c[3])
        : "r"(a[0]), "r"(a[1]), "r"(a[2]), "r"(a[3]), "r"(b[0]), "r"(b[1]));
}

// ================= warp-MMA GEMM (bf16x3 emulated fp32) =================
// D[M,N] = A[M,K] * B^T  (B stored [N,K] K-major). A fp32 always.
// MODE_B: 0 = B pre-split bf16 (Bh/Bl), 1 = B fp32 [N,K] split on the fly (TILE_N=128)
// EPI: 0 none, 1 relu, 2 self-mask scores, 3 cross-mask scores
template<int TILE_N, int MODE_B, int EPI>
__global__ void __launch_bounds__(256) mm_gemm(
    const float* __restrict__ A, int lda, long sA, long sA2,
    const void* __restrict__ Bhv, const void* __restrict__ Blv, int ldb, long sB, long sB2,
    float* __restrict__ C, int ldc, long sC, long sC2,
    int K, int bdiv, const int* __restrict__ tok)
{
    constexpr int WGM = (TILE_N == 128) ? 2 : 4;
    constexpr int WGN = 8 / WGM;
    constexpr int WTM = 128 / WGM;       // 64 or 32
    constexpr int WTN = TILE_N / WGN;    // 32
    constexpr int MT = WTM / 16;         // 4 or 2
    constexpr int NT = WTN / 8;          // 4
    constexpr int PITCH = 72;            // bf16 elems per smem row (144B, conflict-free)

    extern __shared__ char smem[];
    __nv_bfloat16* sAhi = (__nv_bfloat16*)smem;
    __nv_bfloat16* sAlo = sAhi + 128 * PITCH;
    __nv_bfloat16* sBhi = sAlo + 128 * PITCH;
    __nv_bfloat16* sBlo = sBhi + TILE_N * PITCH;
    uint32_t uAhi = smem_u32(sAhi), uAlo = smem_u32(sAlo);
    uint32_t uBhi = smem_u32(sBhi), uBlo = smem_u32(sBlo);

    int tid = threadIdx.x, warp = tid >> 5, lane = tid & 31;
    int z = blockIdx.z, zo = z / bdiv, zi = z % bdiv;
    A += (long)zo * sA + (long)zi * sA2;
    C += (long)zo * sC + (long)zi * sC2;
    const __nv_bfloat16* Bhi = nullptr; const __nv_bfloat16* Blo = nullptr; const float* Bf = nullptr;
    if (MODE_B == 0) {
        Bhi = (const __nv_bfloat16*)Bhv + (long)zo * sB + (long)zi * sB2;
        Blo = (const __nv_bfloat16*)Blv + (long)zo * sB + (long)zi * sB2;
    } else {
        Bf = (const float*)Bhv + (long)zo * sB + (long)zi * sB2;
    }
    int m0 = blockIdx.y * 128, n0 = blockIdx.x * TILE_N;

    int wm = warp & (WGM - 1), wn = warp / WGM;
    int mbase = wm * WTM, nbase = wn * WTN;

    float acc[MT][NT][4];
#pragma unroll
    for (int i = 0; i < MT; i++)
#pragma unroll
        for (int j = 0; j < NT; j++)
#pragma unroll
            for (int c = 0; c < 4; c++) acc[i][j][c] = 0.0f;

    // precomputed ldmatrix smem offsets (element units; lane-dependent parts)
    const int a_row = (lane & 15), a_koff = ((lane >> 4) << 3);
    const int b_row = ((lane >> 4) << 3) + (lane & 7), b_koff = (((lane >> 3) & 1) << 3);

    const int arow_ld = tid >> 1, aseg = (tid & 1) * 32;
    const float* Arow = A + (long)(m0 + arow_ld) * lda + aseg;

    for (int k0 = 0; k0 < K; k0 += 64) {
        // ---- stage A tile: 128 x 64 fp32 -> hi/lo bf16 ----
        {
            const float* p = Arow + k0;
#pragma unroll
            for (int c = 0; c < 4; c++) {
                float buf[8];
                *(float4*)buf = *(const float4*)(p + c * 8);
                *(float4*)(buf + 4) = *(const float4*)(p + c * 8 + 4);
                uint4 H, L; split8(buf, H, L);
                uint32_t off = (uint32_t)(arow_ld * PITCH + aseg + c * 8) * 2;
                STS128(uAhi + off, H);
                STS128(uAlo + off, L);
            }
        }
        // ---- stage B tile ----
        if (MODE_B == 0) {
#pragma unroll
            for (int e = tid * 8; e < TILE_N * 64; e += 2048) {
                int n = e >> 6, col = e & 63;
                long gb = (long)(n0 + n) * ldb + k0 + col;
                uint4 H = *(const uint4*)(Bhi + gb);
                uint4 L = *(const uint4*)(Blo + gb);
                uint32_t off = (uint32_t)(n * PITCH + col) * 2;
                STS128(uBhi + off, H);
                STS128(uBlo + off, L);
            }
        } else {
            const float* p = Bf + (long)(n0 + arow_ld) * ldb + k0 + aseg;
#pragma unroll
            for (int c = 0; c < 4; c++) {
                float buf[8];
                *(float4*)buf = *(const float4*)(p + c * 8);
                *(float4*)(buf + 4) = *(const float4*)(p + c * 8 + 4);
                uint4 H, L; split8(buf, H, L);
                uint32_t off = (uint32_t)(arow_ld * PITCH + aseg + c * 8) * 2;
                STS128(uBhi + off, H);
                STS128(uBlo + off, L);
            }
        }
        __syncthreads();

        // ---- 3 passes: hi*hi, hi*lo, lo*hi ----
#pragma unroll
        for (int pass = 0; pass < 3; pass++) {
            uint32_t pA = (pass == 2) ? uAlo : uAhi;
            uint32_t pB = (pass == 1) ? uBlo : uBhi;
#pragma unroll
            for (int ks = 0; ks < 4; ks++) {
                uint32_t af[MT][4];
#pragma unroll
                for (int mi = 0; mi < MT; mi++)
                    ldm4(af[mi], pA + (uint32_t)((mbase + mi * 16 + a_row) * PITCH + ks * 16 + a_koff) * 2);
                uint32_t bfr[NT][2];
#pragma unroll
                for (int nj = 0; nj < NT / 2; nj++) {
                    uint32_t t4[4];
                    ldm4(t4, pB + (uint32_t)((nbase + nj * 16 + b_row) * PITCH + ks * 16 + b_koff) * 2);
                    bfr[2 * nj][0] = t4[0]; bfr[2 * nj][1] = t4[1];
                    bfr[2 * nj + 1][0] = t4[2]; bfr[2 * nj + 1][1] = t4[3];
                }
#pragma unroll
                for (int mi = 0; mi < MT; mi++)
#pragma unroll
                    for (int ni = 0; ni < NT; ni++)
                        mma16816(acc[mi][ni], af[mi], bfr[ni]);
            }
        }
        __syncthreads();
    }

    // ---- epilogue ----
#pragma unroll
    for (int mi = 0; mi < MT; mi++) {
#pragma unroll
        for (int ni = 0; ni < NT; ni++) {
            int m = m0 + mbase + mi * 16 + (lane >> 2);
            int n = n0 + nbase + ni * 8 + (lane & 3) * 2;
            float* c0 = acc[mi][ni];
            if (EPI <= 1) {
                float2 v0 = make_float2(c0[0], c0[1]);
                float2 v1 = make_float2(c0[2], c0[3]);
                if (EPI == 1) {
                    v0.x = fmaxf(v0.x, 0.f); v0.y = fmaxf(v0.y, 0.f);
                    v1.x = fmaxf(v1.x, 0.f); v1.y = fmaxf(v1.y, 0.f);
                }
                *(float2*)(C + (long)m * ldc + n) = v0;
                *(float2*)(C + (long)(m + 8) * ldc + n) = v1;
            } else {
                const int* tz = tok + zo * 1024;
                int t0 = tz[n], t1 = tz[n + 1];
                float2 v0, v1;
                bool m00 = (EPI == 2) ? ((n > m) || (t0 == 0)) : (t0 == 0);
                bool m01 = (EPI == 2) ? ((n + 1 > m) || (t1 == 0)) : (t1 == 0);
                bool m10 = (EPI == 2) ? ((n > m + 8) || (t0 == 0)) : (t0 == 0);
                bool m11 = (EPI == 2) ? ((n + 1 > m + 8) || (t1 == 0)) : (t1 == 0);
                v0.x = m00 ? -1e9f : c0[0] * 0.125f;
                v0.y = m01 ? -1e9f : c0[1] * 0.125f;
                v1.x = m10 ? -1e9f : c0[2] * 0.125f;
                v1.y = m11 ? -1e9f : c0[3] * 0.125f;
                *(float2*)(C + (long)m * ldc + n) = v0;
                *(float2*)(C + (long)(m + 8) * ldc + n) = v1;
            }
        }
    }
}

// ---------------- weight transpose + split: W[K,N] -> Wt[N,K] hi/lo bf16 ----------------
__global__ void wt_build(const float* __restrict__ W, __nv_bfloat16* __restrict__ Whi,
                         __nv_bfloat16* __restrict__ Wlo, int Kd, int Nd)
{
    __shared__ float t[32][33];
    int k0 = blockIdx.y * 32, n0 = blockIdx.x * 32;
    t[threadIdx.y][threadIdx.x] = W[(long)(k0 + threadIdx.y) * Nd + n0 + threadIdx.x];
    __syncthreads();
    float v = t[threadIdx.x][threadIdx.y];
    long o = (long)(n0 + threadIdx.y) * Kd + k0 + threadIdx.x;
    __nv_bfloat16 h = __float2bfloat16(v);
    Whi[o] = h;
    Wlo[o] = __float2bfloat16(v - __bfloat162float(h));
}

// ---------------- V transpose + split ----------------
__global__ void vt_build(const float* __restrict__ v, __nv_bfloat16* __restrict__ vhi,
                         __nv_bfloat16* __restrict__ vlo)
{
    int z = blockIdx.z, b = z >> 3, h = z & 7;
    __shared__ float t[32][33];
    int s0 = blockIdx.x * 32, d0 = blockIdx.y * 32;
    t[threadIdx.y][threadIdx.x] = v[(long)(b * Ss + s0 + threadIdx.y) * Dm + h * 64 + d0 + threadIdx.x];
    __syncthreads();
    float val = t[threadIdx.x][threadIdx.y];
    long o = (long)(z * 64 + d0 + threadIdx.y) * Ss + s0 + threadIdx.x;
    __nv_bfloat16 hb = __float2bfloat16(val);
    vhi[o] = hb;
    vlo[o] = __float2bfloat16(val - __bfloat162float(hb));
}

// ---------------- embedding + sinusoidal PE (padding_idx = 0) ----------------
__global__ void embed_k(const int* __restrict__ dec, const float* __restrict__ emb,
                        float* __restrict__ x)
{
    int bt = blockIdx.x;
    int tpos = bt & (Tt - 1);
    int tokv = dec[bt];
    int t = threadIdx.x;
    const double c0 = -9.210340371976184 / (double)Dm;
#pragma unroll
    for (int i = 0; i < 4; i++) {
        int d = t + 128 * i;
        int pair = d >> 1;
        double div = exp((double)(2 * pair) * c0);
        double ang = (double)tpos * div;
        float pe = (float)((d & 1) ? cos(ang) : sin(ang));
        float e = (tokv == 0) ? 0.0f : emb[(size_t)tokv * Dm + d];
        x[(size_t)bt * Dm + d] = e + pe;
    }
}

// ---------------- row softmax over 1024 ----------------
__global__ void softmax_k(float* __restrict__ S)
{
    float* row = S + (size_t)blockIdx.x * 1024;
    int t = threadIdx.x;
    float v[4];
    float m = -INFINITY;
#pragma unroll
    for (int i = 0; i < 4; i++) { v[i] = row[t + i * 256]; m = fmaxf(m, v[i]); }
    __shared__ float red[256];
    red[t] = m; __syncthreads();
    for (int s = 128; s > 0; s >>= 1) { if (t < s) red[t] = fmaxf(red[t], red[t + s]); __syncthreads(); }
    m = red[0]; __syncthreads();
    float sum = 0.0f;
#pragma unroll
    for (int i = 0; i < 4; i++) { v[i] = expf(v[i] - m); sum += v[i]; }
    red[t] = sum; __syncthreads();
    for (int s = 128; s > 0; s >>= 1) { if (t < s) red[t] += red[t + s]; __syncthreads(); }
    float inv = 1.0f / red[0];
#pragma unroll
    for (int i = 0; i < 4; i++) row[t + i * 256] = v[i] * inv;
}

// ---------------- out = LayerNorm(a + b) over D=512 ----------------
__global__ void add_ln_k(const float* __restrict__ A, const float* __restrict__ Bres,
                         float* __restrict__ O)
{
    size_t r = blockIdx.x;
    const float* a = A + r * Dm;
    const float* b = Bres + r * Dm;
    int t = threadIdx.x;
    float v[4];
    float s = 0.0f;
#pragma unroll
    for (int i = 0; i < 4; i++) { v[i] = a[t + 128 * i] + b[t + 128 * i]; s += v[i]; }
    __shared__ float red[128];
    red[t] = s; __syncthreads();
    for (int st = 64; st > 0; st >>= 1) { if (t < st) red[t] += red[t + st]; __syncthreads(); }
    float mu = red[0] * (1.0f / Dm);
    __syncthreads();
    float s2 = 0.0f;
#pragma unroll
    for (int i = 0; i < 4; i++) { float d = v[i] - mu; s2 += d * d; }
    red[t] = s2; __syncthreads();
    for (int st = 64; st > 0; st >>= 1) { if (t < st) red[t] += red[t + st]; __syncthreads(); }
    float inv = rsqrtf(red[0] * (1.0f / Dm) + 1e-5f);
#pragma unroll
    for (int i = 0; i < 4; i++) O[r * Dm + t + 128 * i] = (v[i] - mu) * inv;
}

// ---------------- host ----------------
static float* sym_ptr(const void* sym) { void* p = nullptr; cudaGetSymbolAddress(&p, sym); return (float*)p; }
static __nv_bfloat16* sym_ptr_bf(const void* sym) { void* p = nullptr; cudaGetSymbolAddress(&p, sym); return (__nv_bfloat16*)p; }

#define SM_N128 ((128 + 128 + 128 + 128) * 72 * 2)
#define SM_N64  ((128 + 128 + 64 + 64) * 72 * 2)

extern "C" void kernel_launch(void* const* d_in, const int* in_sizes, int n_in,
                              void* d_out, int out_size)
{
    const int*   dec      = (const int*)d_in[0];
    const int*   enc_in   = (const int*)d_in[1];
    const float* enc_out  = (const float*)d_in[2];
    const float* emb      = (const float*)d_in[3];
    const float* Wq_self  = (const float*)d_in[4];
    const float* Wk_self  = (const float*)d_in[5];
    const float* Wv_self  = (const float*)d_in[6];
    const float* Wo_self  = (const float*)d_in[7];
    const float* Wq_cross = (const float*)d_in[8];
    const float* Wk_cross = (const float*)d_in[9];
    const float* Wv_cross = (const float*)d_in[10];
    const float* Wo_cross = (const float*)d_in[11];
    const float* W1       = (const float*)d_in[12];
    const float* W2       = (const float*)d_in[13];

    float* x   = sym_ptr(g_x);
    float* q   = sym_ptr(g_q);
    float* k   = sym_ptr(g_k);
    float* v   = sym_ptr(g_v);
    float* s   = sym_ptr(g_s);
    float* ctx = sym_ptr(g_ctx);
    float* hbf = sym_ptr(g_h);
    float* t1  = sym_ptr(g_t);
    __nv_bfloat16* wthi = sym_ptr_bf(g_wthi);
    __nv_bfloat16* wtlo = sym_ptr_bf(g_wtlo);
    __nv_bfloat16* vthi = sym_ptr_bf(g_vthi);
    __nv_bfloat16* vtlo = sym_ptr_bf(g_vtlo);

    cudaFuncSetAttribute(mm_gemm<128,0,0>, cudaFuncAttributeMaxDynamicSharedMemorySize, SM_N128);
    cudaFuncSetAttribute(mm_gemm<128,0,1>, cudaFuncAttributeMaxDynamicSharedMemorySize, SM_N128);
    cudaFuncSetAttribute(mm_gemm<128,1,2>, cudaFuncAttributeMaxDynamicSharedMemorySize, SM_N128);
    cudaFuncSetAttribute(mm_gemm<128,1,3>, cudaFuncAttributeMaxDynamicSharedMemorySize, SM_N128);
    cudaFuncSetAttribute(mm_gemm<64,0,0>,  cudaFuncAttributeMaxDynamicSharedMemorySize, SM_N64);

    const int M = Bz * Tt;
    const long TT = (long)Tt * Ss;
    const long TD = (long)Tt * Dm;
    const long SD = (long)Ss * Dm;

    dim3 b32(32, 32);
    for (int l = 0; l < NL; l++) {
        long wb = (long)l * WT_L;
        const float* srcs[8] = {
            Wq_self + (long)l * Dm * Dm, Wk_self + (long)l * Dm * Dm,
            Wv_self + (long)l * Dm * Dm, Wo_self + (long)l * Dm * Dm,
            Wq_cross + (long)l * Dm * Dm, Wk_cross + (long)l * Dm * Dm,
            Wv_cross + (long)l * Dm * Dm, Wo_cross + (long)l * Dm * Dm };
        for (int mi = 0; mi < 8; mi++)
            wt_build<<<dim3(16, 16), b32>>>(srcs[mi], wthi + wb + mi * 262144, wtlo + wb + mi * 262144, Dm, Dm);
        wt_build<<<dim3(64, 16), b32>>>(W1 + (long)l * Dm * FFd, wthi + wb + 2097152, wtlo + wb + 2097152, Dm, FFd);
        wt_build<<<dim3(16, 64), b32>>>(W2 + (long)l * FFd * Dm, wthi + wb + 3145728, wtlo + wb + 3145728, FFd, Dm);
    }

    embed_k<<<Bz * Tt, 128>>>(dec, emb, x);

    dim3 gProj(Dm / 128, M / 128, 1);
    dim3 gFF1(FFd / 128, M / 128, 1);
    dim3 gFF2(Dm / 128, M / 128, 1);
    dim3 gSc(Ss / 128, Tt / 128, Bz * Hh);
    dim3 gCtx(1, Tt / 128, Bz * Hh);
    dim3 gVt(Ss / 32, 2, Bz * Hh);

    for (int l = 0; l < NL; l++) {
        long wb = (long)l * WT_L;
        const __nv_bfloat16* wqs_h = wthi + wb + 0 * 262144; const __nv_bfloat16* wqs_l = wtlo + wb + 0 * 262144;
        const __nv_bfloat16* wks_h = wthi + wb + 1 * 262144; const __nv_bfloat16* wks_l = wtlo + wb + 1 * 262144;
        const __nv_bfloat16* wvs_h = wthi + wb + 2 * 262144; const __nv_bfloat16* wvs_l = wtlo + wb + 2 * 262144;
        const __nv_bfloat16* wos_h = wthi + wb + 3 * 262144; const __nv_bfloat16* wos_l = wtlo + wb + 3 * 262144;
        const __nv_bfloat16* wqc_h = wthi + wb + 4 * 262144; const __nv_bfloat16* wqc_l = wtlo + wb + 4 * 262144;
        const __nv_bfloat16* wkc_h = wthi + wb + 5 * 262144; const __nv_bfloat16* wkc_l = wtlo + wb + 5 * 262144;
        const __nv_bfloat16* wvc_h = wthi + wb + 6 * 262144; const __nv_bfloat16* wvc_l = wtlo + wb + 6 * 262144;
        const __nv_bfloat16* woc_h = wthi + wb + 7 * 262144; const __nv_bfloat16* woc_l = wtlo + wb + 7 * 262144;
        const __nv_bfloat16* w1_h = wthi + wb + 2097152; const __nv_bfloat16* w1_l = wtlo + wb + 2097152;
        const __nv_bfloat16* w2_h = wthi + wb + 3145728; const __nv_bfloat16* w2_l = wtlo + wb + 3145728;

        // ---- self-attention ----
        mm_gemm<128,0,0><<<gProj, 256, SM_N128>>>(x, Dm, 0, 0, wqs_h, wqs_l, Dm, 0, 0, q, Dm, 0, 0, Dm, 1, nullptr);
        mm_gemm<128,0,0><<<gProj, 256, SM_N128>>>(x, Dm, 0, 0, wks_h, wks_l, Dm, 0, 0, k, Dm, 0, 0, Dm, 1, nullptr);
        mm_gemm<128,0,0><<<gProj, 256, SM_N128>>>(x, Dm, 0, 0, wvs_h, wvs_l, Dm, 0, 0, v, Dm, 0, 0, Dm, 1, nullptr);
        mm_gemm<128,1,2><<<gSc, 256, SM_N128>>>(q, Dm, TD, 64, k, nullptr, Dm, SD, 64, s, Ss, 8 * TT, TT, DKh, 8, dec);
        softmax_k<<<Bz * Hh * Tt, 256>>>(s);
        vt_build<<<gVt, b32>>>(v, vthi, vtlo);
        mm_gemm<64,0,0><<<gCtx, 256, SM_N64>>>(s, Ss, 8 * TT, TT, vthi, vtlo, Ss, (long)8 * 64 * Ss, (long)64 * Ss,
                                               ctx, Dm, TD, 64, Ss, 8, nullptr);
        mm_gemm<128,0,0><<<gProj, 256, SM_N128>>>(ctx, Dm, 0, 0, wos_h, wos_l, Dm, 0, 0, t1, Dm, 0, 0, Dm, 1, nullptr);
        add_ln_k<<<M, 128>>>(t1, x, x);

        // ---- cross-attention ----
        mm_gemm<128,0,0><<<gProj, 256, SM_N128>>>(x, Dm, 0, 0, wqc_h, wqc_l, Dm, 0, 0, q, Dm, 0, 0, Dm, 1, nullptr);
        mm_gemm<128,0,0><<<gProj, 256, SM_N128>>>(enc_out, Dm, 0, 0, wkc_h, wkc_l, Dm, 0, 0, k, Dm, 0, 0, Dm, 1, nullptr);
        mm_gemm<128,0,0><<<gProj, 256, SM_N128>>>(enc_out, Dm, 0, 0, wvc_h, wvc_l, Dm, 0, 0, v, Dm, 0, 0, Dm, 1, nullptr);
        mm_gemm<128,1,3><<<gSc, 256, SM_N128>>>(q, Dm, TD, 64, k, nullptr, Dm, SD, 64, s, Ss, 8 * TT, TT, DKh, 8, enc_in);
        softmax_k<<<Bz * Hh * Tt, 256>>>(s);
        vt_build<<<gVt, b32>>>(v, vthi, vtlo);
        mm_gemm<64,0,0><<<gCtx, 256, SM_N64>>>(s, Ss, 8 * TT, TT, vthi, vtlo, Ss, (long)8 * 64 * Ss, (long)64 * Ss,
                                               ctx, Dm, TD, 64, Ss, 8, nullptr);
        mm_gemm<128,0,0><<<gProj, 256, SM_N128>>>(ctx, Dm, 0, 0, woc_h, woc_l, Dm, 0, 0, t1, Dm, 0, 0, Dm, 1, nullptr);
        add_ln_k<<<M, 128>>>(t1, x, x);

        // ---- FFN ----
        mm_gemm<128,0,1><<<gFF1, 256, SM_N128>>>(x, Dm, 0, 0, w1_h, w1_l, Dm, 0, 0, hbf, FFd, 0, 0, Dm, 1, nullptr);
        mm_gemm<128,0,0><<<gFF2, 256, SM_N128>>>(hbf, FFd, 0, 0, w2_h, w2_l, FFd, 0, 0, t1, Dm, 0, 0, FFd, 1, nullptr);
        add_ln_k<<<M, 128>>>(t1, x, x);
    }

    cudaMemcpyAsync(d_out, x, (size_t)M * Dm * sizeof(float), cudaMemcpyDeviceToDevice);
}

// round 7
// speedup vs baseline: 4.3963x; 1.3530x over previous
#include <cuda_runtime.h>
#include <cuda_bf16.h>
#include <math.h>
#include <stdint.h>

#define Bz 8
#define Tt 1024
#define Ss 1024
#define Dm 512
#define Hh 8
#define DKh 64
#define FFd 2048
#define NL 6

// ---------------- scratch (device globals) ----------------
__device__ __align__(256) float g_x  [Bz*Tt*Dm];
__device__ __align__(256) float g_v  [Bz*Ss*Dm];
__device__ __align__(256) float g_s  [(size_t)Bz*Hh*Tt*Ss];
__device__ __align__(256) float g_t  [Bz*Tt*Dm];

__device__ __align__(256) __nv_bfloat16 g_xhi[Bz*Tt*Dm];
__device__ __align__(256) __nv_bfloat16 g_xlo[Bz*Tt*Dm];
__device__ __align__(256) __nv_bfloat16 g_qhi[Bz*Tt*Dm];
__device__ __align__(256) __nv_bfloat16 g_qlo[Bz*Tt*Dm];
__device__ __align__(256) __nv_bfloat16 g_khi[Bz*Ss*Dm];
__device__ __align__(256) __nv_bfloat16 g_klo[Bz*Ss*Dm];
__device__ __align__(256) __nv_bfloat16 g_chi[Bz*Tt*Dm];
__device__ __align__(256) __nv_bfloat16 g_clo[Bz*Tt*Dm];
__device__ __align__(256) __nv_bfloat16 g_hhi[Bz*Tt*FFd];
__device__ __align__(256) __nv_bfloat16 g_hlo[Bz*Tt*FFd];
__device__ __align__(256) __nv_bfloat16 g_shi[(size_t)Bz*Hh*Tt*Ss];
__device__ __align__(256) __nv_bfloat16 g_slo[(size_t)Bz*Hh*Tt*Ss];
__device__ __align__(256) __nv_bfloat16 g_ehi[Bz*Ss*Dm];
__device__ __align__(256) __nv_bfloat16 g_elo[Bz*Ss*Dm];

#define WT_L 4194304
__device__ __align__(256) __nv_bfloat16 g_wthi[(size_t)NL*WT_L];
__device__ __align__(256) __nv_bfloat16 g_wtlo[(size_t)NL*WT_L];
__device__ __align__(256) __nv_bfloat16 g_vthi[Bz*Hh*DKh*Ss];
__device__ __align__(256) __nv_bfloat16 g_vtlo[Bz*Hh*DKh*Ss];

// ---------------- helpers ----------------
__device__ __forceinline__ uint32_t smem_u32(const void* p) {
    uint32_t a;
    asm("{ .reg .u64 t; cvta.to.shared.u64 t, %1; cvt.u32.u64 %0, t; }" : "=r"(a) : "l"(p));
    return a;
}
__device__ __forceinline__ void cpa16(uint32_t s, const void* g) {
    asm volatile("cp.async.ca.shared.global [%0], [%1], 16;" :: "r"(s), "l"(g));
}
#define CP_COMMIT() asm volatile("cp.async.commit_group;" ::: "memory")
#define CP_WAIT1()  asm volatile("cp.async.wait_group 1;" ::: "memory")
#define CP_WAIT0()  asm volatile("cp.async.wait_group 0;" ::: "memory")

__device__ __forceinline__ void ldm4(uint32_t* r, uint32_t addr) {
    asm volatile("ldmatrix.sync.aligned.m8n8.x4.shared.b16 {%0,%1,%2,%3}, [%4];"
        : "=r"(r[0]), "=r"(r[1]), "=r"(r[2]), "=r"(r[3]) : "r"(addr));
}
__device__ __forceinline__ void mma16816(float* c, const uint32_t* a, const uint32_t* b) {
    asm volatile("mma.sync.aligned.m16n8k16.row.col.f32.bf16.bf16.f32 "
        "{%0,%1,%2,%3}, {%4,%5,%6,%7}, {%8,%9}, {%0,%1,%2,%3};"
        : "+f"(c[0]), "+f"(c[1]), "+f"(c[2]), "+f"(c[3])
        : "r"(a[0]), "r"(a[1]), "r"(a[2]), "r"(a[3]), "r"(b[0]), "r"(b[1]));
}
__device__ __forceinline__ void split_store(float a, float b,
                                            __nv_bfloat16* hi, __nv_bfloat16* lo) {
    __nv_bfloat16 ha = __float2bfloat16(a), hb = __float2bfloat16(b);
    __nv_bfloat162 H; H.x = ha; H.y = hb;
    __nv_bfloat162 L;
    L.x = __float2bfloat16(a - __bfloat162float(ha));
    L.y = __float2bfloat16(b - __bfloat162float(hb));
    *(__nv_bfloat162*)hi = H;
    *(__nv_bfloat162*)lo = L;
}

// ================= pipelined warp-MMA GEMM (bf16x3 emulated fp32) =================
// D[M,N] = A[M,K] * B^T; all operands pre-split hi/lo bf16, K-major rows.
// EPI: 0 plain, 1 relu, 2 self-mask scores, 3 cross-mask scores
// Outputs: Cf (fp32, optional), Chi/Clo (split bf16, optional).
template<int TILE_N, int EPI>
__global__ void __launch_bounds__(256) mm2(
    const __nv_bfloat16* __restrict__ Ah, const __nv_bfloat16* __restrict__ Al,
    int lda, long sA, long sA2,
    const __nv_bfloat16* __restrict__ Bh, const __nv_bfloat16* __restrict__ Bl,
    int ldb, long sB, long sB2,
    float* __restrict__ Cf, __nv_bfloat16* __restrict__ Chi, __nv_bfloat16* __restrict__ Clo,
    int ldc, long sC, long sC2,
    int K, int bdiv, const int* __restrict__ tok)
{
    constexpr int WGM = (TILE_N == 128) ? 2 : 4;
    constexpr int WGN = 8 / WGM;
    constexpr int WTM = 128 / WGM;       // 64 or 32
    constexpr int WTN = TILE_N / WGN;    // 32
    constexpr int MT = WTM / 16;
    constexpr int NT = WTN / 8;
    constexpr int PITCH = 72;            // 144B rows, ldmatrix conflict-free
    constexpr int STAGE_B = (256 + 2 * TILE_N) * PITCH * 2;

    extern __shared__ char smem[];
    uint32_t sb = smem_u32(smem);

    int tid = threadIdx.x, warp = tid >> 5, lane = tid & 31;
    int z = blockIdx.z, zo = z / bdiv, zi = z % bdiv;
    long aoff = (long)zo * sA + (long)zi * sA2;
    long boff = (long)zo * sB + (long)zi * sB2;
    long coff = (long)zo * sC + (long)zi * sC2;
    Ah += aoff; Al += aoff; Bh += boff; Bl += boff;
    int m0 = blockIdx.y * 128, n0 = blockIdx.x * TILE_N;

    int wm = warp & (WGM - 1), wn = warp / WGM;
    int mbase = wm * WTM, nbase = wn * WTN;

    float acc[MT][NT][4];
#pragma unroll
    for (int i = 0; i < MT; i++)
#pragma unroll
        for (int j = 0; j < NT; j++)
#pragma unroll
            for (int c = 0; c < 4; c++) acc[i][j][c] = 0.0f;

    const int a_row = (lane & 15), a_koff = ((lane >> 4) << 3);
    const int b_row = ((lane >> 4) << 3) + (lane & 7), b_koff = (((lane >> 3) & 1) << 3);

    auto issue = [&](int stage, int k0) {
        uint32_t base = sb + stage * STAGE_B;
        uint32_t uAhi = base, uAlo = base + 128 * PITCH * 2;
        uint32_t uBhi = base + 256 * PITCH * 2, uBlo = uBhi + TILE_N * PITCH * 2;
#pragma unroll
        for (int i = 0; i < 4; i++) {
            int idx = tid + 256 * i;
            int r = idx >> 3, c = idx & 7;
            long g = (long)(m0 + r) * lda + k0 + c * 8;
            uint32_t so = (uint32_t)(r * PITCH + c * 8) * 2;
            cpa16(uAhi + so, Ah + g);
            cpa16(uAlo + so, Al + g);
        }
#pragma unroll
        for (int i = 0; i < TILE_N / 32; i++) {
            int idx = tid + 256 * i;
            int r = idx >> 3, c = idx & 7;
            long g = (long)(n0 + r) * ldb + k0 + c * 8;
            uint32_t so = (uint32_t)(r * PITCH + c * 8) * 2;
            cpa16(uBhi + so, Bh + g);
            cpa16(uBlo + so, Bl + g);
        }
        CP_COMMIT();
    };

    int nch = K >> 6;
    issue(0, 0);
    if (nch > 1) issue(1, 64);

    for (int it = 0; it < nch; it++) {
        if (it + 2 <= nch) CP_WAIT1(); else CP_WAIT0();
        __syncthreads();
        uint32_t base = sb + (it & 1) * STAGE_B;
        uint32_t uA[2] = { base, base + 128 * PITCH * 2 };
        uint32_t uB[2] = { base + 256 * PITCH * 2, base + 256 * PITCH * 2 + TILE_N * PITCH * 2 };

#pragma unroll
        for (int pass = 0; pass < 3; pass++) {
            uint32_t pA = uA[pass == 2];
            uint32_t pB = uB[pass == 1];
#pragma unroll
            for (int ks = 0; ks < 4; ks++) {
                uint32_t af[MT][4];
#pragma unroll
                for (int mi = 0; mi < MT; mi++)
                    ldm4(af[mi], pA + (uint32_t)((mbase + mi * 16 + a_row) * PITCH + ks * 16 + a_koff) * 2);
                uint32_t bfr[NT][2];
#pragma unroll
                for (int nj = 0; nj < NT / 2; nj++) {
                    uint32_t t4[4];
                    ldm4(t4, pB + (uint32_t)((nbase + nj * 16 + b_row) * PITCH + ks * 16 + b_koff) * 2);
                    bfr[2 * nj][0] = t4[0]; bfr[2 * nj][1] = t4[1];
                    bfr[2 * nj + 1][0] = t4[2]; bfr[2 * nj + 1][1] = t4[3];
                }
#pragma unroll
                for (int mi = 0; mi < MT; mi++)
#pragma unroll
                    for (int ni = 0; ni < NT; ni++)
                        mma16816(acc[mi][ni], af[mi], bfr[ni]);
            }
        }
        __syncthreads();
        if (it + 2 < nch) issue(it & 1, (it + 2) * 64);
    }

    // ---- epilogue ----
    if (Cf) Cf += coff;
    if (Chi) { Chi += coff; Clo += coff; }
#pragma unroll
    for (int mi = 0; mi < MT; mi++) {
#pragma unroll
        for (int ni = 0; ni < NT; ni++) {
            int m = m0 + mbase + mi * 16 + (lane >> 2);
            int n = n0 + nbase + ni * 8 + (lane & 3) * 2;
            float* c0 = acc[mi][ni];
            if (EPI <= 1) {
                float a0 = c0[0], a1 = c0[1], a2 = c0[2], a3 = c0[3];
                if (EPI == 1) {
                    a0 = fmaxf(a0, 0.f); a1 = fmaxf(a1, 0.f);
                    a2 = fmaxf(a2, 0.f); a3 = fmaxf(a3, 0.f);
                }
                if (Cf) {
                    *(float2*)(Cf + (long)m * ldc + n) = make_float2(a0, a1);
                    *(float2*)(Cf + (long)(m + 8) * ldc + n) = make_float2(a2, a3);
                }
                if (Chi) {
                    split_store(a0, a1, Chi + (long)m * ldc + n, Clo + (long)m * ldc + n);
                    split_store(a2, a3, Chi + (long)(m + 8) * ldc + n, Clo + (long)(m + 8) * ldc + n);
                }
            } else {
                const int* tz = tok + zo * 1024;
                int t0 = tz[n], t1 = tz[n + 1];
                float2 v0, v1;
                bool m00 = (EPI == 2) ? ((n > m) || (t0 == 0)) : (t0 == 0);
                bool m01 = (EPI == 2) ? ((n + 1 > m) || (t1 == 0)) : (t1 == 0);
                bool m10 = (EPI == 2) ? ((n > m + 8) || (t0 == 0)) : (t0 == 0);
                bool m11 = (EPI == 2) ? ((n + 1 > m + 8) || (t1 == 0)) : (t1 == 0);
                v0.x = m00 ? -1e9f : c0[0] * 0.125f;
                v0.y = m01 ? -1e9f : c0[1] * 0.125f;
                v1.x = m10 ? -1e9f : c0[2] * 0.125f;
                v1.y = m11 ? -1e9f : c0[3] * 0.125f;
                *(float2*)(Cf + (long)m * ldc + n) = v0;
                *(float2*)(Cf + (long)(m + 8) * ldc + n) = v1;
            }
        }
    }
}

// ---------------- weight transpose + split, batched over layers ----------------
__global__ void wt_build(const float* __restrict__ W, __nv_bfloat16* __restrict__ Whi,
                         __nv_bfloat16* __restrict__ Wlo, int Kd, int Nd,
                         long srcStride, long dstStride)
{
    int l = blockIdx.z;
    W += (long)l * srcStride; Whi += (long)l * dstStride; Wlo += (long)l * dstStride;
    __shared__ float t[32][33];
    int k0 = blockIdx.y * 32, n0 = blockIdx.x * 32;
    t[threadIdx.y][threadIdx.x] = W[(long)(k0 + threadIdx.y) * Nd + n0 + threadIdx.x];
    __syncthreads();
    float v = t[threadIdx.x][threadIdx.y];
    long o = (long)(n0 + threadIdx.y) * Kd + k0 + threadIdx.x;
    __nv_bfloat16 h = __float2bfloat16(v);
    Whi[o] = h;
    Wlo[o] = __float2bfloat16(v - __bfloat162float(h));
}

// ---------------- V transpose + split ----------------
__global__ void vt_build(const float* __restrict__ v, __nv_bfloat16* __restrict__ vhi,
                         __nv_bfloat16* __restrict__ vlo)
{
    int z = blockIdx.z, b = z >> 3, h = z & 7;
    __shared__ float t[32][33];
    int s0 = blockIdx.x * 32, d0 = blockIdx.y * 32;
    t[threadIdx.y][threadIdx.x] = v[(long)(b * Ss + s0 + threadIdx.y) * Dm + h * 64 + d0 + threadIdx.x];
    __syncthreads();
    float val = t[threadIdx.x][threadIdx.y];
    long o = (long)(z * 64 + d0 + threadIdx.y) * Ss + s0 + threadIdx.x;
    __nv_bfloat16 hb = __float2bfloat16(val);
    vhi[o] = hb;
    vlo[o] = __float2bfloat16(val - __bfloat162float(hb));
}

// ---------------- embedding + PE, writes fp32 + split ----------------
__global__ void embed_k(const int* __restrict__ dec, const float* __restrict__ emb,
                        float* __restrict__ x, __nv_bfloat16* __restrict__ xhi,
                        __nv_bfloat16* __restrict__ xlo)
{
    int bt = blockIdx.x;
    int tpos = bt & (Tt - 1);
    int tokv = dec[bt];
    int d0 = threadIdx.x * 4;
    const double c0 = -9.210340371976184 / (double)Dm;
    float vals[4];
#pragma unroll
    for (int i = 0; i < 4; i++) {
        int d = d0 + i;
        int pair = d >> 1;
        double div = exp((double)(2 * pair) * c0);
        double ang = (double)tpos * div;
        float pe = (float)((d & 1) ? cos(ang) : sin(ang));
        float e = (tokv == 0) ? 0.0f : emb[(size_t)tokv * Dm + d];
        vals[i] = e + pe;
    }
    size_t o = (size_t)bt * Dm + d0;
    *(float4*)(x + o) = *(float4*)vals;
    split_store(vals[0], vals[1], xhi + o, xlo + o);
    split_store(vals[2], vals[3], xhi + o + 2, xlo + o + 2);
}

// ---------------- enc_out split ----------------
__global__ void enc_split(const float* __restrict__ e, __nv_bfloat16* __restrict__ ehi,
                          __nv_bfloat16* __restrict__ elo)
{
    size_t o = (size_t)blockIdx.x * Dm + threadIdx.x * 4;
    float4 v = *(const float4*)(e + o);
    split_store(v.x, v.y, ehi + o, elo + o);
    split_store(v.z, v.w, ehi + o + 2, elo + o + 2);
}

// ---------------- row softmax over 1024, writes split bf16 ----------------
__global__ void softmax_k(const float* __restrict__ S, __nv_bfloat16* __restrict__ Phi,
                          __nv_bfloat16* __restrict__ Plo)
{
    size_t rb = (size_t)blockIdx.x * 1024;
    const float* row = S + rb;
    int t = threadIdx.x;
    float4 v = *(const float4*)(row + t * 4);
    float m = fmaxf(fmaxf(v.x, v.y), fmaxf(v.z, v.w));
    __shared__ float red[256];
    red[t] = m; __syncthreads();
    for (int s = 128; s > 0; s >>= 1) { if (t < s) red[t] = fmaxf(red[t], red[t + s]); __syncthreads(); }
    m = red[0]; __syncthreads();
    v.x = expf(v.x - m); v.y = expf(v.y - m); v.z = expf(v.z - m); v.w = expf(v.w - m);
    float sum = v.x + v.y + v.z + v.w;
    red[t] = sum; __syncthreads();
    for (int s = 128; s > 0; s >>= 1) { if (t < s) red[t] += red[t + s]; __syncthreads(); }
    float inv = 1.0f / red[0];
    v.x *= inv; v.y *= inv; v.z *= inv; v.w *= inv;
    split_store(v.x, v.y, Phi + rb + t * 4, Plo + rb + t * 4);
    split_store(v.z, v.w, Phi + rb + t * 4 + 2, Plo + rb + t * 4 + 2);
}

// ---------------- out = LayerNorm(a + b); writes fp32 + split ----------------
__global__ void add_ln_k(const float* __restrict__ A, const float* __restrict__ Bres,
                         float* __restrict__ O, __nv_bfloat16* __restrict__ Ohi,
                         __nv_bfloat16* __restrict__ Olo)
{
    size_t r = blockIdx.x;
    int t = threadIdx.x;
    size_t o = r * Dm + t * 4;
    float4 va = *(const float4*)(A + o);
    float4 vb = *(const float4*)(Bres + o);
    float v[4] = { va.x + vb.x, va.y + vb.y, va.z + vb.z, va.w + vb.w };
    float s = v[0] + v[1] + v[2] + v[3];
    __shared__ float red[128];
    red[t] = s; __syncthreads();
    for (int st = 64; st > 0; st >>= 1) { if (t < st) red[t] += red[t + st]; __syncthreads(); }
    float mu = red[0] * (1.0f / Dm);
    __syncthreads();
    float s2 = 0.0f;
#pragma unroll
    for (int i = 0; i < 4; i++) { float d = v[i] - mu; s2 += d * d; }
    red[t] = s2; __syncthreads();
    for (int st = 64; st > 0; st >>= 1) { if (t < st) red[t] += red[t + st]; __syncthreads(); }
    float inv = rsqrtf(red[0] * (1.0f / Dm) + 1e-5f);
    float out[4];
#pragma unroll
    for (int i = 0; i < 4; i++) out[i] = (v[i] - mu) * inv;
    *(float4*)(O + o) = *(float4*)out;
    split_store(out[0], out[1], Ohi + o, Olo + o);
    split_store(out[2], out[3], Ohi + o + 2, Olo + o + 2);
}

// ---------------- host ----------------
static float* sym_ptr(const void* sym) { void* p = nullptr; cudaGetSymbolAddress(&p, sym); return (float*)p; }
static __nv_bfloat16* sym_bf(const void* sym) { void* p = nullptr; cudaGetSymbolAddress(&p, sym); return (__nv_bfloat16*)p; }

#define SM_N128 (2 * (256 + 256) * 72 * 2)
#define SM_N64  (2 * (256 + 128) * 72 * 2)

extern "C" void kernel_launch(void* const* d_in, const int* in_sizes, int n_in,
                              void* d_out, int out_size)
{
    const int*   dec      = (const int*)d_in[0];
    const int*   enc_in   = (const int*)d_in[1];
    const float* enc_out  = (const float*)d_in[2];
    const float* emb      = (const float*)d_in[3];
    const float* Wq_self  = (const float*)d_in[4];
    const float* Wk_self  = (const float*)d_in[5];
    const float* Wv_self  = (const float*)d_in[6];
    const float* Wo_self  = (const float*)d_in[7];
    const float* Wq_cross = (const float*)d_in[8];
    const float* Wk_cross = (const float*)d_in[9];
    const float* Wv_cross = (const float*)d_in[10];
    const float* Wo_cross = (const float*)d_in[11];
    const float* W1       = (const float*)d_in[12];
    const float* W2       = (const float*)d_in[13];

    float* x   = sym_ptr(g_x);
    float* v   = sym_ptr(g_v);
    float* s   = sym_ptr(g_s);
    float* t1  = sym_ptr(g_t);
    __nv_bfloat16* xhi = sym_bf(g_xhi); __nv_bfloat16* xlo = sym_bf(g_xlo);
    __nv_bfloat16* qhi = sym_bf(g_qhi); __nv_bfloat16* qlo = sym_bf(g_qlo);
    __nv_bfloat16* khi = sym_bf(g_khi); __nv_bfloat16* klo = sym_bf(g_klo);
    __nv_bfloat16* chi = sym_bf(g_chi); __nv_bfloat16* clo = sym_bf(g_clo);
    __nv_bfloat16* hhi = sym_bf(g_hhi); __nv_bfloat16* hlo = sym_bf(g_hlo);
    __nv_bfloat16* shi = sym_bf(g_shi); __nv_bfloat16* slo = sym_bf(g_slo);
    __nv_bfloat16* ehi = sym_bf(g_ehi); __nv_bfloat16* elo = sym_bf(g_elo);
    __nv_bfloat16* wthi = sym_bf(g_wthi); __nv_bfloat16* wtlo = sym_bf(g_wtlo);
    __nv_bfloat16* vthi = sym_bf(g_vthi); __nv_bfloat16* vtlo = sym_bf(g_vtlo);

    cudaFuncSetAttribute(mm2<128,0>, cudaFuncAttributeMaxDynamicSharedMemorySize, SM_N128);
    cudaFuncSetAttribute(mm2<128,1>, cudaFuncAttributeMaxDynamicSharedMemorySize, SM_N128);
    cudaFuncSetAttribute(mm2<128,2>, cudaFuncAttributeMaxDynamicSharedMemorySize, SM_N128);
    cudaFuncSetAttribute(mm2<128,3>, cudaFuncAttributeMaxDynamicSharedMemorySize, SM_N128);
    cudaFuncSetAttribute(mm2<64,0>,  cudaFuncAttributeMaxDynamicSharedMemorySize, SM_N64);

    const int M = Bz * Tt;
    const long TT = (long)Tt * Ss;
    const long TD = (long)Tt * Dm;
    const long SD = (long)Ss * Dm;

    // ---- build transposed/split weights (batched over layers via grid.z) ----
    dim3 b32(32, 32);
    const float* projSrc[8] = { Wq_self, Wk_self, Wv_self, Wo_self,
                                Wq_cross, Wk_cross, Wv_cross, Wo_cross };
    for (int mi = 0; mi < 8; mi++)
        wt_build<<<dim3(16, 16, NL), b32>>>(projSrc[mi], wthi + mi * 262144, wtlo + mi * 262144,
                                            Dm, Dm, (long)Dm * Dm, WT_L);
    wt_build<<<dim3(64, 16, NL), b32>>>(W1, wthi + 2097152, wtlo + 2097152, Dm, FFd, (long)Dm * FFd, WT_L);
    wt_build<<<dim3(16, 64, NL), b32>>>(W2, wthi + 3145728, wtlo + 3145728, FFd, Dm, (long)FFd * Dm, WT_L);

    enc_split<<<Bz * Ss, 128>>>(enc_out, ehi, elo);
    embed_k<<<Bz * Tt, 128>>>(dec, emb, x, xhi, xlo);

    dim3 gProj(Dm / 128, M / 128, 1);
    dim3 gFF1(FFd / 128, M / 128, 1);
    dim3 gFF2(Dm / 128, M / 128, 1);
    dim3 gSc(Ss / 128, Tt / 128, Bz * Hh);
    dim3 gCtx(1, Tt / 128, Bz * Hh);
    dim3 gVt(Ss / 32, 2, Bz * Hh);

    for (int l = 0; l < NL; l++) {
        long wb = (long)l * WT_L;
        const __nv_bfloat16* W_h[10]; const __nv_bfloat16* W_l[10];
        for (int mi = 0; mi < 8; mi++) { W_h[mi] = wthi + wb + mi * 262144; W_l[mi] = wtlo + wb + mi * 262144; }
        W_h[8] = wthi + wb + 2097152; W_l[8] = wtlo + wb + 2097152;
        W_h[9] = wthi + wb + 3145728; W_l[9] = wtlo + wb + 3145728;

        // ---- self-attention ----
        mm2<128,0><<<gProj, 256, SM_N128>>>(xhi, xlo, Dm, 0, 0, W_h[0], W_l[0], Dm, 0, 0,
                                            nullptr, qhi, qlo, Dm, 0, 0, Dm, 1, nullptr);
        mm2<128,0><<<gProj, 256, SM_N128>>>(xhi, xlo, Dm, 0, 0, W_h[1], W_l[1], Dm, 0, 0,
                                            nullptr, khi, klo, Dm, 0, 0, Dm, 1, nullptr);
        mm2<128,0><<<gProj, 256, SM_N128>>>(xhi, xlo, Dm, 0, 0, W_h[2], W_l[2], Dm, 0, 0,
                                            v, nullptr, nullptr, Dm, 0, 0, Dm, 1, nullptr);
        mm2<128,2><<<gSc, 256, SM_N128>>>(qhi, qlo, Dm, TD, 64, khi, klo, Dm, SD, 64,
                                          s, nullptr, nullptr, Ss, 8 * TT, TT, DKh, 8, dec);
        softmax_k<<<Bz * Hh * Tt, 256>>>(s, shi, slo);
        vt_build<<<gVt, b32>>>(v, vthi, vtlo);
        mm2<64,0><<<gCtx, 256, SM_N64>>>(shi, slo, Ss, 8 * TT, TT, vthi, vtlo, Ss, (long)8 * 64 * Ss, (long)64 * Ss,
                                         nullptr, chi, clo, Dm, TD, 64, Ss, 8, nullptr);
        mm2<128,0><<<gProj, 256, SM_N128>>>(chi, clo, Dm, 0, 0, W_h[3], W_l[3], Dm, 0, 0,
                                            t1, nullptr, nullptr, Dm, 0, 0, Dm, 1, nullptr);
        add_ln_k<<<M, 128>>>(t1, x, x, xhi, xlo);

        // ---- cross-attention ----
        mm2<128,0><<<gProj, 256, SM_N128>>>(xhi, xlo, Dm, 0, 0, W_h[4], W_l[4], Dm, 0, 0,
                                            nullptr, qhi, qlo, Dm, 0, 0, Dm, 1, nullptr);
        mm2<128,0><<<gProj, 256, SM_N128>>>(ehi, elo, Dm, 0, 0, W_h[5], W_l[5], Dm, 0, 0,
                                            nullptr, khi, klo, Dm, 0, 0, Dm, 1, nullptr);
        mm2<128,0><<<gProj, 256, SM_N128>>>(ehi, elo, Dm, 0, 0, W_h[6], W_l[6], Dm, 0, 0,
                                            v, nullptr, nullptr, Dm, 0, 0, Dm, 1, nullptr);
        mm2<128,3><<<gSc, 256, SM_N128>>>(qhi, qlo, Dm, TD, 64, khi, klo, Dm, SD, 64,
                                          s, nullptr, nullptr, Ss, 8 * TT, TT, DKh, 8, enc_in);
        softmax_k<<<Bz * Hh * Tt, 256>>>(s, shi, slo);
        vt_build<<<gVt, b32>>>(v, vthi, vtlo);
        mm2<64,0><<<gCtx, 256, SM_N64>>>(shi, slo, Ss, 8 * TT, TT, vthi, vtlo, Ss, (long)8 * 64 * Ss, (long)64 * Ss,
                                         nullptr, chi, clo, Dm, TD, 64, Ss, 8, nullptr);
        mm2<128,0><<<gProj, 256, SM_N128>>>(chi, clo, Dm, 0, 0, W_h[7], W_l[7], Dm, 0, 0,
                                            t1, nullptr, nullptr, Dm, 0, 0, Dm, 1, nullptr);
        add_ln_k<<<M, 128>>>(t1, x, x, xhi, xlo);

        // ---- FFN ----
        mm2<128,1><<<gFF1, 256, SM_N128>>>(xhi, xlo, Dm, 0, 0, W_h[8], W_l[8], Dm, 0, 0,
                                           nullptr, hhi, hlo, FFd, 0, 0, Dm, 1, nullptr);
        mm2<128,0><<<gFF2, 256, SM_N128>>>(hhi, hlo, FFd, 0, 0, W_h[9], W_l[9], FFd, 0, 0,
                                           t1, nullptr, nullptr, Dm, 0, 0, FFd, 1, nullptr);
        add_ln_k<<<M, 128>>>(t1, x, x, xhi, xlo);
    }

    cudaMemcpyAsync(d_out, x, (size_t)M * Dm * sizeof(float), cudaMemcpyDeviceToDevice);
}

// round 8
// speedup vs baseline: 6.0953x; 1.3865x over previous
#include <cuda_runtime.h>
#include <cuda_bf16.h>
#include <math.h>
#include <stdint.h>

#define Bz 8
#define Tt 1024
#define Ss 1024
#define Dm 512
#define Hh 8
#define DKh 64
#define FFd 2048
#define NL 6

// ---------------- scratch (device globals) ----------------
__device__ __align__(256) float g_x  [Bz*Tt*Dm];
__device__ __align__(256) float g_v  [Bz*Ss*Dm];
__device__ __align__(256) float g_t  [Bz*Tt*Dm];

__device__ __align__(256) __nv_bfloat16 g_xhi[Bz*Tt*Dm];
__device__ __align__(256) __nv_bfloat16 g_xlo[Bz*Tt*Dm];
__device__ __align__(256) __nv_bfloat16 g_qhi[Bz*Tt*Dm];
__device__ __align__(256) __nv_bfloat16 g_qlo[Bz*Tt*Dm];
__device__ __align__(256) __nv_bfloat16 g_khi[Bz*Ss*Dm];
__device__ __align__(256) __nv_bfloat16 g_klo[Bz*Ss*Dm];
__device__ __align__(256) __nv_bfloat16 g_chi[Bz*Tt*Dm];
__device__ __align__(256) __nv_bfloat16 g_clo[Bz*Tt*Dm];
__device__ __align__(256) __nv_bfloat16 g_hhi[Bz*Tt*FFd];
__device__ __align__(256) __nv_bfloat16 g_hlo[Bz*Tt*FFd];
__device__ __align__(256) __nv_bfloat16 g_ehi[Bz*Ss*Dm];
__device__ __align__(256) __nv_bfloat16 g_elo[Bz*Ss*Dm];

#define WT_L 4194304
__device__ __align__(256) __nv_bfloat16 g_wthi[(size_t)NL*WT_L];
__device__ __align__(256) __nv_bfloat16 g_wtlo[(size_t)NL*WT_L];
__device__ __align__(256) __nv_bfloat16 g_vthi[Bz*Hh*DKh*Ss];
__device__ __align__(256) __nv_bfloat16 g_vtlo[Bz*Hh*DKh*Ss];

// ---------------- helpers ----------------
__device__ __forceinline__ uint32_t smem_u32(const void* p) {
    uint32_t a;
    asm("{ .reg .u64 t; cvta.to.shared.u64 t, %1; cvt.u32.u64 %0, t; }" : "=r"(a) : "l"(p));
    return a;
}
__device__ __forceinline__ void cpa16(uint32_t s, const void* g) {
    asm volatile("cp.async.ca.shared.global [%0], [%1], 16;" :: "r"(s), "l"(g));
}
#define CP_COMMIT() asm volatile("cp.async.commit_group;" ::: "memory")
#define CP_WAIT1()  asm volatile("cp.async.wait_group 1;" ::: "memory")
#define CP_WAIT0()  asm volatile("cp.async.wait_group 0;" ::: "memory")

__device__ __forceinline__ void ldm4(uint32_t* r, uint32_t addr) {
    asm volatile("ldmatrix.sync.aligned.m8n8.x4.shared.b16 {%0,%1,%2,%3}, [%4];"
        : "=r"(r[0]), "=r"(r[1]), "=r"(r[2]), "=r"(r[3]) : "r"(addr));
}
__device__ __forceinline__ void mma16816(float* c, const uint32_t* a, const uint32_t* b) {
    asm volatile("mma.sync.aligned.m16n8k16.row.col.f32.bf16.bf16.f32 "
        "{%0,%1,%2,%3}, {%4,%5,%6,%7}, {%8,%9}, {%0,%1,%2,%3};"
        : "+f"(c[0]), "+f"(c[1]), "+f"(c[2]), "+f"(c[3])
        : "r"(a[0]), "r"(a[1]), "r"(a[2]), "r"(a[3]), "r"(b[0]), "r"(b[1]));
}
__device__ __forceinline__ void split_store(float a, float b,
                                            __nv_bfloat16* hi, __nv_bfloat16* lo) {
    __nv_bfloat16 ha = __float2bfloat16(a), hb = __float2bfloat16(b);
    __nv_bfloat162 H; H.x = ha; H.y = hb;
    __nv_bfloat162 L;
    L.x = __float2bfloat16(a - __bfloat162float(ha));
    L.y = __float2bfloat16(b - __bfloat162float(hb));
    *(__nv_bfloat162*)hi = H;
    *(__nv_bfloat162*)lo = L;
}
__device__ __forceinline__ void split_pack(float a, float b, uint32_t& H, uint32_t& L) {
    __nv_bfloat16 ha = __float2bfloat16(a), hb = __float2bfloat16(b);
    __nv_bfloat162 Hv; Hv.x = ha; Hv.y = hb;
    __nv_bfloat162 Lv;
    Lv.x = __float2bfloat16(a - __bfloat162float(ha));
    Lv.y = __float2bfloat16(b - __bfloat162float(hb));
    H = *reinterpret_cast<uint32_t*>(&Hv);
    L = *reinterpret_cast<uint32_t*>(&Lv);
}

// ================= pipelined warp-MMA GEMM (bf16x3 emulated fp32) =================
template<int TILE_N, int EPI>
__global__ void __launch_bounds__(256) mm2(
    const __nv_bfloat16* __restrict__ Ah, const __nv_bfloat16* __restrict__ Al,
    int lda, long sA, long sA2,
    const __nv_bfloat16* __restrict__ Bh, const __nv_bfloat16* __restrict__ Bl,
    int ldb, long sB, long sB2,
    float* __restrict__ Cf, __nv_bfloat16* __restrict__ Chi, __nv_bfloat16* __restrict__ Clo,
    int ldc, long sC, long sC2,
    int K, int bdiv, const int* __restrict__ tok)
{
    constexpr int WGM = (TILE_N == 128) ? 2 : 4;
    constexpr int WGN = 8 / WGM;
    constexpr int WTM = 128 / WGM;
    constexpr int WTN = TILE_N / WGN;
    constexpr int MT = WTM / 16;
    constexpr int NT = WTN / 8;
    constexpr int PITCH = 72;
    constexpr int STAGE_B = (256 + 2 * TILE_N) * PITCH * 2;

    extern __shared__ char smem[];
    uint32_t sb = smem_u32(smem);

    int tid = threadIdx.x, warp = tid >> 5, lane = tid & 31;
    int z = blockIdx.z, zo = z / bdiv, zi = z % bdiv;
    long aoff = (long)zo * sA + (long)zi * sA2;
    long boff = (long)zo * sB + (long)zi * sB2;
    long coff = (long)zo * sC + (long)zi * sC2;
    Ah += aoff; Al += aoff; Bh += boff; Bl += boff;
    int m0 = blockIdx.y * 128, n0 = blockIdx.x * TILE_N;

    int wm = warp & (WGM - 1), wn = warp / WGM;
    int mbase = wm * WTM, nbase = wn * WTN;

    float acc[MT][NT][4];
#pragma unroll
    for (int i = 0; i < MT; i++)
#pragma unroll
        for (int j = 0; j < NT; j++)
#pragma unroll
            for (int c = 0; c < 4; c++) acc[i][j][c] = 0.0f;

    const int a_row = (lane & 15), a_koff = ((lane >> 4) << 3);
    const int b_row = ((lane >> 4) << 3) + (lane & 7), b_koff = (((lane >> 3) & 1) << 3);

    auto issue = [&](int stage, int k0) {
        uint32_t base = sb + stage * STAGE_B;
        uint32_t uAhi = base, uAlo = base + 128 * PITCH * 2;
        uint32_t uBhi = base + 256 * PITCH * 2, uBlo = uBhi + TILE_N * PITCH * 2;
#pragma unroll
        for (int i = 0; i < 4; i++) {
            int idx = tid + 256 * i;
            int r = idx >> 3, c = idx & 7;
            long g = (long)(m0 + r) * lda + k0 + c * 8;
            uint32_t so = (uint32_t)(r * PITCH + c * 8) * 2;
            cpa16(uAhi + so, Ah + g);
            cpa16(uAlo + so, Al + g);
        }
#pragma unroll
        for (int i = 0; i < TILE_N / 32; i++) {
            int idx = tid + 256 * i;
            int r = idx >> 3, c = idx & 7;
            long g = (long)(n0 + r) * ldb + k0 + c * 8;
            uint32_t so = (uint32_t)(r * PITCH + c * 8) * 2;
            cpa16(uBhi + so, Bh + g);
            cpa16(uBlo + so, Bl + g);
        }
        CP_COMMIT();
    };

    int nch = K >> 6;
    issue(0, 0);
    if (nch > 1) issue(1, 64);

    for (int it = 0; it < nch; it++) {
        if (it + 2 <= nch) CP_WAIT1(); else CP_WAIT0();
        __syncthreads();
        uint32_t base = sb + (it & 1) * STAGE_B;
        uint32_t uA[2] = { base, base + 128 * PITCH * 2 };
        uint32_t uB[2] = { base + 256 * PITCH * 2, base + 256 * PITCH * 2 + TILE_N * PITCH * 2 };

#pragma unroll
        for (int pass = 0; pass < 3; pass++) {
            uint32_t pA = uA[pass == 2];
            uint32_t pB = uB[pass == 1];
#pragma unroll
            for (int ks = 0; ks < 4; ks++) {
                uint32_t af[MT][4];
#pragma unroll
                for (int mi = 0; mi < MT; mi++)
                    ldm4(af[mi], pA + (uint32_t)((mbase + mi * 16 + a_row) * PITCH + ks * 16 + a_koff) * 2);
                uint32_t bfr[NT][2];
#pragma unroll
                for (int nj = 0; nj < NT / 2; nj++) {
                    uint32_t t4[4];
                    ldm4(t4, pB + (uint32_t)((nbase + nj * 16 + b_row) * PITCH + ks * 16 + b_koff) * 2);
                    bfr[2 * nj][0] = t4[0]; bfr[2 * nj][1] = t4[1];
                    bfr[2 * nj + 1][0] = t4[2]; bfr[2 * nj + 1][1] = t4[3];
                }
#pragma unroll
                for (int mi = 0; mi < MT; mi++)
#pragma unroll
                    for (int ni = 0; ni < NT; ni++)
                        mma16816(acc[mi][ni], af[mi], bfr[ni]);
            }
        }
        __syncthreads();
        if (it + 2 < nch) issue(it & 1, (it + 2) * 64);
    }

    if (Cf) Cf += coff;
    if (Chi) { Chi += coff; Clo += coff; }
#pragma unroll
    for (int mi = 0; mi < MT; mi++) {
#pragma unroll
        for (int ni = 0; ni < NT; ni++) {
            int m = m0 + mbase + mi * 16 + (lane >> 2);
            int n = n0 + nbase + ni * 8 + (lane & 3) * 2;
            float* c0 = acc[mi][ni];
            float a0 = c0[0], a1 = c0[1], a2 = c0[2], a3 = c0[3];
            if (EPI == 1) {
                a0 = fmaxf(a0, 0.f); a1 = fmaxf(a1, 0.f);
                a2 = fmaxf(a2, 0.f); a3 = fmaxf(a3, 0.f);
            }
            if (Cf) {
                *(float2*)(Cf + (long)m * ldc + n) = make_float2(a0, a1);
                *(float2*)(Cf + (long)(m + 8) * ldc + n) = make_float2(a2, a3);
            }
            if (Chi) {
                split_store(a0, a1, Chi + (long)m * ldc + n, Clo + (long)m * ldc + n);
                split_store(a2, a3, Chi + (long)(m + 8) * ldc + n, Clo + (long)(m + 8) * ldc + n);
            }
        }
    }
}

// ================= fused flash attention (bf16x3, online softmax) =================
// Q[T,64] per (b,h) vs K[S,64], V^T[64,S]; ctx out split bf16 into [B*T, Dm] head slice.
#define KPITCH 72
#define VPITCH 136
#define FL_STAGE 71680      // Khi 18432 + Klo 18432 + Vhi 17408 + Vlo 17408
#define FL_SMEM  (2 * FL_STAGE + 512)

template<int CAUSAL>
__global__ void __launch_bounds__(256) flash(
    const __nv_bfloat16* __restrict__ Qh, const __nv_bfloat16* __restrict__ Ql,
    const __nv_bfloat16* __restrict__ Kh, const __nv_bfloat16* __restrict__ Kl,
    const __nv_bfloat16* __restrict__ Vth, const __nv_bfloat16* __restrict__ Vtl,
    __nv_bfloat16* __restrict__ Chi, __nv_bfloat16* __restrict__ Clo,
    const int* __restrict__ tok)
{
    extern __shared__ char smem[];
    uint32_t sb = smem_u32(smem);
    float* msk = (float*)(smem + 2 * FL_STAGE);

    int tid = threadIdx.x, warp = tid >> 5, lane = tid & 31;
    int z = blockIdx.y, b = z >> 3, h = z & 7;
    int q0 = blockIdx.x * 128;
    int mbase = warp * 16;

    const __nv_bfloat16* Qhb = Qh + ((long)(b * Tt + q0)) * Dm + h * 64;
    const __nv_bfloat16* Qlb = Ql + ((long)(b * Tt + q0)) * Dm + h * 64;
    const __nv_bfloat16* Khb = Kh + ((long)b * Ss) * Dm + h * 64;
    const __nv_bfloat16* Klb = Kl + ((long)b * Ss) * Dm + h * 64;
    const __nv_bfloat16* Vhb = Vth + (long)z * 64 * Ss;
    const __nv_bfloat16* Vlb = Vtl + (long)z * 64 * Ss;
    const int* tokb = tok + b * 1024;

    const int a_row = (lane & 15), a_koff = ((lane >> 4) << 3);
    const int b_row = ((lane >> 4) << 3) + (lane & 7), b_koff = (((lane >> 3) & 1) << 3);

    // ---- stage Q into stage0 K area, load Q fragments ----
    {
        uint32_t uQh = sb, uQl = sb + 128 * KPITCH * 2;
#pragma unroll
        for (int i = 0; i < 4; i++) {
            int idx = tid + 256 * i;
            int r = idx >> 3, c = idx & 7;
            long g = (long)r * Dm + c * 8;
            uint32_t so = (uint32_t)(r * KPITCH + c * 8) * 2;
            cpa16(uQh + so, Qhb + g);
            cpa16(uQl + so, Qlb + g);
        }
        CP_COMMIT(); CP_WAIT0();
        __syncthreads();
    }
    uint32_t qh[4][4], ql[4][4];
#pragma unroll
    for (int ks = 0; ks < 4; ks++) {
        ldm4(qh[ks], sb + (uint32_t)((mbase + a_row) * KPITCH + ks * 16 + a_koff) * 2);
        ldm4(ql[ks], sb + 128 * KPITCH * 2 + (uint32_t)((mbase + a_row) * KPITCH + ks * 16 + a_koff) * 2);
    }
    __syncthreads();

    auto issue = [&](int stage, int kb) {
        uint32_t base = sb + stage * FL_STAGE;
        uint32_t uKhi = base, uKlo = base + 18432;
        uint32_t uVhi = base + 36864, uVlo = base + 54272;
#pragma unroll
        for (int i = 0; i < 4; i++) {
            int idx = tid + 256 * i;
            int r = idx >> 3, c = idx & 7;
            long g = (long)(kb * 128 + r) * Dm + c * 8;
            uint32_t so = (uint32_t)(r * KPITCH + c * 8) * 2;
            cpa16(uKhi + so, Khb + g);
            cpa16(uKlo + so, Klb + g);
        }
#pragma unroll
        for (int i = 0; i < 4; i++) {
            int idx = tid + 256 * i;
            int r = idx >> 4, c = idx & 15;
            long g = (long)r * Ss + kb * 128 + c * 8;
            uint32_t so = (uint32_t)(r * VPITCH + c * 8) * 2;
            cpa16(uVhi + so, Vhb + g);
            cpa16(uVlo + so, Vlb + g);
        }
        CP_COMMIT();
    };

    const float CSC = 0.125f * 1.4426950408889634f;   // scale * log2(e)
    float oacc[8][4];
#pragma unroll
    for (int i = 0; i < 8; i++)
#pragma unroll
        for (int c = 0; c < 4; c++) oacc[i][c] = 0.0f;
    float m0 = -INFINITY, m1 = -INFINITY, l0 = 0.0f, l1 = 0.0f;
    const int qr0 = q0 + mbase + (lane >> 2);
    const int qr1 = qr0 + 8;

    int nkb = CAUSAL ? (q0 / 128 + 1) : (Ss / 128);
    issue(0, 0);
    if (nkb > 1) issue(1, 1);

    for (int kb = 0; kb < nkb; kb++) {
        int tokv = 0;
        if (tid < 128) tokv = tokb[kb * 128 + tid];
        if (kb + 2 <= nkb) CP_WAIT1(); else CP_WAIT0();
        __syncthreads();
        if (tid < 128) msk[tid] = (tokv == 0) ? 1.0f : 0.0f;
        __syncthreads();

        uint32_t base = sb + (kb & 1) * FL_STAGE;
        uint32_t uK[2] = { base, base + 18432 };
        uint32_t uV[2] = { base + 36864, base + 54272 };

        // ---- S = Q K^T (3 passes) ----
        float sacc[16][4];
#pragma unroll
        for (int i = 0; i < 16; i++)
#pragma unroll
            for (int c = 0; c < 4; c++) sacc[i][c] = 0.0f;
#pragma unroll
        for (int pass = 0; pass < 3; pass++) {
            uint32_t (*qr)[4] = (pass == 2) ? ql : qh;
            uint32_t pK = uK[pass == 1];
#pragma unroll
            for (int ks = 0; ks < 4; ks++) {
#pragma unroll
                for (int nj = 0; nj < 8; nj++) {
                    uint32_t t4[4];
                    ldm4(t4, pK + (uint32_t)((nj * 16 + b_row) * KPITCH + ks * 16 + b_koff) * 2);
                    mma16816(sacc[2 * nj], qr[ks], t4);
                    mma16816(sacc[2 * nj + 1], qr[ks], t4 + 2);
                }
            }
        }

        // ---- scale + mask + row max ----
        float mx0 = -INFINITY, mx1 = -INFINITY;
#pragma unroll
        for (int t = 0; t < 16; t++) {
            int cb = t * 8 + (lane & 3) * 2;
            float2 mv = *(float2*)(msk + cb);
            int kg = kb * 128 + cb;
            bool M0 = (mv.x != 0.0f), M1 = (mv.y != 0.0f);
            bool c00 = M0 || (CAUSAL && kg > qr0);
            bool c01 = M1 || (CAUSAL && kg + 1 > qr0);
            bool c10 = M0 || (CAUSAL && kg > qr1);
            bool c11 = M1 || (CAUSAL && kg + 1 > qr1);
            sacc[t][0] = c00 ? -1e9f : sacc[t][0] * CSC;
            sacc[t][1] = c01 ? -1e9f : sacc[t][1] * CSC;
            sacc[t][2] = c10 ? -1e9f : sacc[t][2] * CSC;
            sacc[t][3] = c11 ? -1e9f : sacc[t][3] * CSC;
            mx0 = fmaxf(mx0, fmaxf(sacc[t][0], sacc[t][1]));
            mx1 = fmaxf(mx1, fmaxf(sacc[t][2], sacc[t][3]));
        }
        mx0 = fmaxf(mx0, __shfl_xor_sync(0xffffffffu, mx0, 1));
        mx0 = fmaxf(mx0, __shfl_xor_sync(0xffffffffu, mx0, 2));
        mx1 = fmaxf(mx1, __shfl_xor_sync(0xffffffffu, mx1, 1));
        mx1 = fmaxf(mx1, __shfl_xor_sync(0xffffffffu, mx1, 2));

        float m0n = fmaxf(m0, mx0), m1n = fmaxf(m1, mx1);
        float al0 = exp2f(m0 - m0n), al1 = exp2f(m1 - m1n);
        m0 = m0n; m1 = m1n;
        l0 *= al0; l1 *= al1;
#pragma unroll
        for (int i = 0; i < 8; i++) {
            oacc[i][0] *= al0; oacc[i][1] *= al0;
            oacc[i][2] *= al1; oacc[i][3] *= al1;
        }

        // ---- P = exp2(S - m); PV in two halves ----
        float ls0 = 0.0f, ls1 = 0.0f;
#pragma unroll
        for (int half = 0; half < 2; half++) {
            uint32_t ph[4][4], pl[4][4];
#pragma unroll
            for (int ksv = 0; ksv < 4; ksv++) {
                int tA = half * 8 + ksv * 2, tB = tA + 1;
                float p00 = exp2f(sacc[tA][0] - m0), p01 = exp2f(sacc[tA][1] - m0);
                float p02 = exp2f(sacc[tA][2] - m1), p03 = exp2f(sacc[tA][3] - m1);
                float p10 = exp2f(sacc[tB][0] - m0), p11 = exp2f(sacc[tB][1] - m0);
                float p12 = exp2f(sacc[tB][2] - m1), p13 = exp2f(sacc[tB][3] - m1);
                ls0 += p00 + p01 + p10 + p11;
                ls1 += p02 + p03 + p12 + p13;
                split_pack(p00, p01, ph[ksv][0], pl[ksv][0]);
                split_pack(p02, p03, ph[ksv][1], pl[ksv][1]);
                split_pack(p10, p11, ph[ksv][2], pl[ksv][2]);
                split_pack(p12, p13, ph[ksv][3], pl[ksv][3]);
            }
#pragma unroll
            for (int pass = 0; pass < 3; pass++) {
                uint32_t (*pa)[4] = (pass == 2) ? pl : ph;
                uint32_t pV = uV[pass == 1];
#pragma unroll
                for (int ksv = 0; ksv < 4; ksv++) {
                    int ksg = half * 4 + ksv;
#pragma unroll
                    for (int nj = 0; nj < 4; nj++) {
                        uint32_t t4[4];
                        ldm4(t4, pV + (uint32_t)((nj * 16 + b_row) * VPITCH + ksg * 16 + b_koff) * 2);
                        mma16816(oacc[2 * nj], pa[ksv], t4);
                        mma16816(oacc[2 * nj + 1], pa[ksv], t4 + 2);
                    }
                }
            }
        }
        ls0 += __shfl_xor_sync(0xffffffffu, ls0, 1);
        ls0 += __shfl_xor_sync(0xffffffffu, ls0, 2);
        ls1 += __shfl_xor_sync(0xffffffffu, ls1, 1);
        ls1 += __shfl_xor_sync(0xffffffffu, ls1, 2);
        l0 += ls0; l1 += ls1;

        __syncthreads();
        if (kb + 2 < nkb) issue(kb & 1, kb + 2);
    }

    // ---- epilogue: O / l, split-store into ctx head slice ----
    float il0 = 1.0f / l0, il1 = 1.0f / l1;
    long gr0 = (long)(b * Tt + q0 + mbase + (lane >> 2));
    long gr1 = gr0 + 8;
#pragma unroll
    for (int oi = 0; oi < 8; oi++) {
        int col = h * 64 + oi * 8 + (lane & 3) * 2;
        split_store(oacc[oi][0] * il0, oacc[oi][1] * il0,
                    Chi + gr0 * Dm + col, Clo + gr0 * Dm + col);
        split_store(oacc[oi][2] * il1, oacc[oi][3] * il1,
                    Chi + gr1 * Dm + col, Clo + gr1 * Dm + col);
    }
}

// ---------------- weight transpose + split, batched over layers ----------------
__global__ void wt_build(const float* __restrict__ W, __nv_bfloat16* __restrict__ Whi,
                         __nv_bfloat16* __restrict__ Wlo, int Kd, int Nd,
                         long srcStride, long dstStride)
{
    int l = blockIdx.z;
    W += (long)l * srcStride; Whi += (long)l * dstStride; Wlo += (long)l * dstStride;
    __shared__ float t[32][33];
    int k0 = blockIdx.y * 32, n0 = blockIdx.x * 32;
    t[threadIdx.y][threadIdx.x] = W[(long)(k0 + threadIdx.y) * Nd + n0 + threadIdx.x];
    __syncthreads();
    float v = t[threadIdx.x][threadIdx.y];
    long o = (long)(n0 + threadIdx.y) * Kd + k0 + threadIdx.x;
    __nv_bfloat16 h = __float2bfloat16(v);
    Whi[o] = h;
    Wlo[o] = __float2bfloat16(v - __bfloat162float(h));
}

// ---------------- V transpose + split ----------------
__global__ void vt_build(const float* __restrict__ v, __nv_bfloat16* __restrict__ vhi,
                         __nv_bfloat16* __restrict__ vlo)
{
    int z = blockIdx.z, b = z >> 3, h = z & 7;
    __shared__ float t[32][33];
    int s0 = blockIdx.x * 32, d0 = blockIdx.y * 32;
    t[threadIdx.y][threadIdx.x] = v[(long)(b * Ss + s0 + threadIdx.y) * Dm + h * 64 + d0 + threadIdx.x];
    __syncthreads();
    float val = t[threadIdx.x][threadIdx.y];
    long o = (long)(z * 64 + d0 + threadIdx.y) * Ss + s0 + threadIdx.x;
    __nv_bfloat16 hb = __float2bfloat16(val);
    vhi[o] = hb;
    vlo[o] = __float2bfloat16(val - __bfloat162float(hb));
}

// ---------------- embedding + PE ----------------
__global__ void embed_k(const int* __restrict__ dec, const float* __restrict__ emb,
                        float* __restrict__ x, __nv_bfloat16* __restrict__ xhi,
                        __nv_bfloat16* __restrict__ xlo)
{
    int bt = blockIdx.x;
    int tpos = bt & (Tt - 1);
    int tokv = dec[bt];
    int d0 = threadIdx.x * 4;
    const double c0 = -9.210340371976184 / (double)Dm;
    float vals[4];
#pragma unroll
    for (int i = 0; i < 4; i++) {
        int d = d0 + i;
        int pair = d >> 1;
        double div = exp((double)(2 * pair) * c0);
        double ang = (double)tpos * div;
        float pe = (float)((d & 1) ? cos(ang) : sin(ang));
        float e = (tokv == 0) ? 0.0f : emb[(size_t)tokv * Dm + d];
        vals[i] = e + pe;
    }
    size_t o = (size_t)bt * Dm + d0;
    *(float4*)(x + o) = *(float4*)vals;
    split_store(vals[0], vals[1], xhi + o, xlo + o);
    split_store(vals[2], vals[3], xhi + o + 2, xlo + o + 2);
}

// ---------------- enc_out split ----------------
__global__ void enc_split(const float* __restrict__ e, __nv_bfloat16* __restrict__ ehi,
                          __nv_bfloat16* __restrict__ elo)
{
    size_t o = (size_t)blockIdx.x * Dm + threadIdx.x * 4;
    float4 v = *(const float4*)(e + o);
    split_store(v.x, v.y, ehi + o, elo + o);
    split_store(v.z, v.w, ehi + o + 2, elo + o + 2);
}

// ---------------- out = LayerNorm(a + b) ----------------
__global__ void add_ln_k(const float* __restrict__ A, const float* __restrict__ Bres,
                         float* __restrict__ O, __nv_bfloat16* __restrict__ Ohi,
                         __nv_bfloat16* __restrict__ Olo)
{
    size_t r = blockIdx.x;
    int t = threadIdx.x;
    size_t o = r * Dm + t * 4;
    float4 va = *(const float4*)(A + o);
    float4 vb = *(const float4*)(Bres + o);
    float v[4] = { va.x + vb.x, va.y + vb.y, va.z + vb.z, va.w + vb.w };
    float s = v[0] + v[1] + v[2] + v[3];
    __shared__ float red[128];
    red[t] = s; __syncthreads();
    for (int st = 64; st > 0; st >>= 1) { if (t < st) red[t] += red[t + st]; __syncthreads(); }
    float mu = red[0] * (1.0f / Dm);
    __syncthreads();
    float s2 = 0.0f;
#pragma unroll
    for (int i = 0; i < 4; i++) { float d = v[i] - mu; s2 += d * d; }
    red[t] = s2; __syncthreads();
    for (int st = 64; st > 0; st >>= 1) { if (t < st) red[t] += red[t + st]; __syncthreads(); }
    float inv = rsqrtf(red[0] * (1.0f / Dm) + 1e-5f);
    float out[4];
#pragma unroll
    for (int i = 0; i < 4; i++) out[i] = (v[i] - mu) * inv;
    *(float4*)(O + o) = *(float4*)out;
    split_store(out[0], out[1], Ohi + o, Olo + o);
    split_store(out[2], out[3], Ohi + o + 2, Olo + o + 2);
}

// ---------------- host ----------------
static float* sym_ptr(const void* sym) { void* p = nullptr; cudaGetSymbolAddress(&p, sym); return (float*)p; }
static __nv_bfloat16* sym_bf(const void* sym) { void* p = nullptr; cudaGetSymbolAddress(&p, sym); return (__nv_bfloat16*)p; }

#define SM_N128 (2 * (256 + 256) * 72 * 2)

extern "C" void kernel_launch(void* const* d_in, const int* in_sizes, int n_in,
                              void* d_out, int out_size)
{
    const int*   dec      = (const int*)d_in[0];
    const int*   enc_in   = (const int*)d_in[1];
    const float* enc_out  = (const float*)d_in[2];
    const float* emb      = (const float*)d_in[3];
    const float* Wq_self  = (const float*)d_in[4];
    const float* Wk_self  = (const float*)d_in[5];
    const float* Wv_self  = (const float*)d_in[6];
    const float* Wo_self  = (const float*)d_in[7];
    const float* Wq_cross = (const float*)d_in[8];
    const float* Wk_cross = (const float*)d_in[9];
    const float* Wv_cross = (const float*)d_in[10];
    const float* Wo_cross = (const float*)d_in[11];
    const float* W1       = (const float*)d_in[12];
    const float* W2       = (const float*)d_in[13];

    float* x   = sym_ptr(g_x);
    float* v   = sym_ptr(g_v);
    float* t1  = sym_ptr(g_t);
    __nv_bfloat16* xhi = sym_bf(g_xhi); __nv_bfloat16* xlo = sym_bf(g_xlo);
    __nv_bfloat16* qhi = sym_bf(g_qhi); __nv_bfloat16* qlo = sym_bf(g_qlo);
    __nv_bfloat16* khi = sym_bf(g_khi); __nv_bfloat16* klo = sym_bf(g_klo);
    __nv_bfloat16* chi = sym_bf(g_chi); __nv_bfloat16* clo = sym_bf(g_clo);
    __nv_bfloat16* hhi = sym_bf(g_hhi); __nv_bfloat16* hlo = sym_bf(g_hlo);
    __nv_bfloat16* ehi = sym_bf(g_ehi); __nv_bfloat16* elo = sym_bf(g_elo);
    __nv_bfloat16* wthi = sym_bf(g_wthi); __nv_bfloat16* wtlo = sym_bf(g_wtlo);
    __nv_bfloat16* vthi = sym_bf(g_vthi); __nv_bfloat16* vtlo = sym_bf(g_vtlo);

    cudaFuncSetAttribute(mm2<128,0>, cudaFuncAttributeMaxDynamicSharedMemorySize, SM_N128);
    cudaFuncSetAttribute(mm2<128,1>, cudaFuncAttributeMaxDynamicSharedMemorySize, SM_N128);
    cudaFuncSetAttribute(flash<0>, cudaFuncAttributeMaxDynamicSharedMemorySize, FL_SMEM);
    cudaFuncSetAttribute(flash<1>, cudaFuncAttributeMaxDynamicSharedMemorySize, FL_SMEM);

    const int M = Bz * Tt;

    // ---- build transposed/split weights (batched over layers via grid.z) ----
    dim3 b32(32, 32);
    const float* projSrc[8] = { Wq_self, Wk_self, Wv_self, Wo_self,
                                Wq_cross, Wk_cross, Wv_cross, Wo_cross };
    for (int mi = 0; mi < 8; mi++)
        wt_build<<<dim3(16, 16, NL), b32>>>(projSrc[mi], wthi + mi * 262144, wtlo + mi * 262144,
                                            Dm, Dm, (long)Dm * Dm, WT_L);
    wt_build<<<dim3(64, 16, NL), b32>>>(W1, wthi + 2097152, wtlo + 2097152, Dm, FFd, (long)Dm * FFd, WT_L);
    wt_build<<<dim3(16, 64, NL), b32>>>(W2, wthi + 3145728, wtlo + 3145728, FFd, Dm, (long)FFd * Dm, WT_L);

    enc_split<<<Bz * Ss, 128>>>(enc_out, ehi, elo);
    embed_k<<<Bz * Tt, 128>>>(dec, emb, x, xhi, xlo);

    dim3 gProj(Dm / 128, M / 128, 1);
    dim3 gFF1(FFd / 128, M / 128, 1);
    dim3 gFF2(Dm / 128, M / 128, 1);
    dim3 gFl(Tt / 128, Bz * Hh, 1);
    dim3 gVt(Ss / 32, 2, Bz * Hh);

    for (int l = 0; l < NL; l++) {
        long wb = (long)l * WT_L;
        const __nv_bfloat16* W_h[10]; const __nv_bfloat16* W_l[10];
        for (int mi = 0; mi < 8; mi++) { W_h[mi] = wthi + wb + mi * 262144; W_l[mi] = wtlo + wb + mi * 262144; }
        W_h[8] = wthi + wb + 2097152; W_l[8] = wtlo + wb + 2097152;
        W_h[9] = wthi + wb + 3145728; W_l[9] = wtlo + wb + 3145728;

        // ---- self-attention ----
        mm2<128,0><<<gProj, 256, SM_N128>>>(xhi, xlo, Dm, 0, 0, W_h[0], W_l[0], Dm, 0, 0,
                                            nullptr, qhi, qlo, Dm, 0, 0, Dm, 1, nullptr);
        mm2<128,0><<<gProj, 256, SM_N128>>>(xhi, xlo, Dm, 0, 0, W_h[1], W_l[1], Dm, 0, 0,
                                            nullptr, khi, klo, Dm, 0, 0, Dm, 1, nullptr);
        mm2<128,0><<<gProj, 256, SM_N128>>>(xhi, xlo, Dm, 0, 0, W_h[2], W_l[2], Dm, 0, 0,
                                            v, nullptr, nullptr, Dm, 0, 0, Dm, 1, nullptr);
        vt_build<<<gVt, b32>>>(v, vthi, vtlo);
        flash<1><<<gFl, 256, FL_SMEM>>>(qhi, qlo, khi, klo, vthi, vtlo, chi, clo, dec);
        mm2<128,0><<<gProj, 256, SM_N128>>>(chi, clo, Dm, 0, 0, W_h[3], W_l[3], Dm, 0, 0,
                                            t1, nullptr, nullptr, Dm, 0, 0, Dm, 1, nullptr);
        add_ln_k<<<M, 128>>>(t1, x, x, xhi, xlo);

        // ---- cross-attention ----
        mm2<128,0><<<gProj, 256, SM_N128>>>(xhi, xlo, Dm, 0, 0, W_h[4], W_l[4], Dm, 0, 0,
                                            nullptr, qhi, qlo, Dm, 0, 0, Dm, 1, nullptr);
        mm2<128,0><<<gProj, 256, SM_N128>>>(ehi, elo, Dm, 0, 0, W_h[5], W_l[5], Dm, 0, 0,
                                            nullptr, khi, klo, Dm, 0, 0, Dm, 1, nullptr);
        mm2<128,0><<<gProj, 256, SM_N128>>>(ehi, elo, Dm, 0, 0, W_h[6], W_l[6], Dm, 0, 0,
                                            v, nullptr, nullptr, Dm, 0, 0, Dm, 1, nullptr);
        vt_build<<<gVt, b32>>>(v, vthi, vtlo);
        flash<0><<<gFl, 256, FL_SMEM>>>(qhi, qlo, khi, klo, vthi, vtlo, chi, clo, enc_in);
        mm2<128,0><<<gProj, 256, SM_N128>>>(chi, clo, Dm, 0, 0, W_h[7], W_l[7], Dm, 0, 0,
                                            t1, nullptr, nullptr, Dm, 0, 0, Dm, 1, nullptr);
        add_ln_k<<<M, 128>>>(t1, x, x, xhi, xlo);

        // ---- FFN ----
        mm2<128,1><<<gFF1, 256, SM_N128>>>(xhi, xlo, Dm, 0, 0, W_h[8], W_l[8], Dm, 0, 0,
                                           nullptr, hhi, hlo, FFd, 0, 0, Dm, 1, nullptr);
        mm2<128,0><<<gFF2, 256, SM_N128>>>(hhi, hlo, FFd, 0, 0, W_h[9], W_l[9], FFd, 0, 0,
                                           t1, nullptr, nullptr, Dm, 0, 0, FFd, 1, nullptr);
        add_ln_k<<<M, 128>>>(t1, x, x, xhi, xlo);
    }

    cudaMemcpyAsync(d_out, x, (size_t)M * Dm * sizeof(float), cudaMemcpyDeviceToDevice);
}